// round 2
// baseline (speedup 1.0000x reference)
#include <cuda_runtime.h>
#include <cstdint>
#include <cstdio>

// ===================== problem constants =====================
#define BB 128
#define TT 2048

// ===================== static device scratch =====================
__device__ float g_bufA[(size_t)BB * TT * 175];
__device__ float g_bufB[(size_t)BB * TT * 175];
__device__ float g_mask[(size_t)BB * TT];
__device__ float g_h34[BB * 60];
__device__ float g_z[BB * 30];
__device__ float g_Uc[60 * 180];
__device__ float g_Wc[150 * 180];
__device__ float g_bc[2 * 180];

// ===================== helpers =====================
__host__ __device__ constexpr int padDim(int v) {
    int h = (v + 3) / 4 * 4;
    if (((h / 4) & 1) == 0) h += 4;   // (h/4) odd -> conflict-free 8-way float4 strides
    return h;
}

__device__ __forceinline__ uint32_t smem_u32(const void* p) {
    uint32_t a;
    asm("{ .reg .u64 t; cvta.to.shared.u64 t, %1; cvt.u32.u64 %0, t; }" : "=r"(a) : "l"(p));
    return a;
}
__device__ __forceinline__ uint32_t mapa_shared(uint32_t local, uint32_t rank) {
    uint32_t r;
    asm("mapa.shared::cluster.u32 %0, %1, %2;" : "=r"(r) : "r"(local), "r"(rank));
    return r;
}
__device__ __forceinline__ void st_cluster_f32(uint32_t addr, float v) {
    asm volatile("st.shared::cluster.b32 [%0], %1;" :: "r"(addr), "r"(__float_as_uint(v)));
}
__device__ __forceinline__ void cluster_sync_() {
    asm volatile("barrier.cluster.arrive.aligned;" ::: "memory");
    asm volatile("barrier.cluster.wait.aligned;" ::: "memory");
}
__device__ __forceinline__ void cp_async4(uint32_t dst, const void* src) {
    asm volatile("cp.async.ca.shared.global [%0], [%1], 4;" :: "r"(dst), "l"(src));
}
__device__ __forceinline__ void cp_commit() {
    asm volatile("cp.async.commit_group;" ::: "memory");
}
__device__ __forceinline__ void cp_wait0() {
    asm volatile("cp.async.wait_group 0;" ::: "memory");
}

// packed f32x2 ops (Blackwell)
__device__ __forceinline__ void ffma2(unsigned long long &c, unsigned long long a,
                                      unsigned long long b) {
    asm("fma.rn.f32x2 %0, %1, %2, %3;" : "=l"(c) : "l"(a), "l"(b), "l"(c));
}
__device__ __forceinline__ unsigned long long addf2(unsigned long long a, unsigned long long b) {
    unsigned long long c;
    asm("add.rn.f32x2 %0, %1, %2;" : "=l"(c) : "l"(a), "l"(b));
    return c;
}
__device__ __forceinline__ float hsum2(unsigned long long v) {
    float a, b;
    asm("mov.b64 {%0,%1}, %2;" : "=f"(a), "=f"(b) : "l"(v));
    return a + b;
}

__device__ __forceinline__ float hsig(float v) { return fminf(fmaxf(0.2f * v + 0.5f, 0.f), 1.f); }
__device__ __forceinline__ float sigm(float v) { return 1.f / (1.f + expf(-v)); }

// ===================== persistent GRU kernel =====================
// Cluster of 8 CTAs = 8 batch rows; CTA r owns hidden tile r (JT units).
// Thread = (ks, b, jj): K dimension split KS ways, reduced via warp shfl.
// Packed f32x2 FMAs along K (2 MACs/instr). x_{t+1} prefetched via cp.async.
// One cluster barrier per step; h exchanged via DSMEM stores.
template <int H, int I, int KS, int NTH, bool HARDSIG, bool TANHACT, bool USEMASK, bool WRITESEQ>
__global__ void __cluster_dims__(8, 1, 1) __launch_bounds__(NTH, 1)
gru_kernel(const float* __restrict__ in_seq, const float* __restrict__ U,
           const float* __restrict__ W, const float* __restrict__ bias,
           const float* __restrict__ mask, float* __restrict__ out_seq)
{
    constexpr int GJ = 8, BT = 8;
    constexpr int JT = (H + GJ - 1) / GJ;
    constexpr int HP = padDim(H), IP = padDim(I);
    constexpr int HPG = HP / 4, IPG = IP / 4;
    static_assert(BT * JT * KS <= NTH, "thread budget");

    extern __shared__ float smem[];
    float* sUz = smem;
    float* sUr = sUz + JT * HP;
    float* sUh = sUr + JT * HP;
    float* sWz = sUh + JT * HP;
    float* sWr = sWz + JT * IP;
    float* sWh = sWr + JT * IP;
    float* sh  = sWh + JT * IP;          // 2 * BT * HP (double buffer)
    float* sx  = sh  + 2 * BT * HP;      // 2 * BT * IP (double buffer)
    float* sbz = sx  + 2 * BT * IP;
    float* sbr = sbz + JT;
    float* sbxh = sbr + JT;
    float* sbrh = sbxh + JT;
    float* smk  = sbrh + JT;             // 2 * BT

    const int tid  = threadIdx.x;
    const int rank = blockIdx.x & 7;
    const int ci   = blockIdx.x >> 3;
    const int b0   = ci * BT;
    const int j0   = rank * JT;

    constexpr int SM_TOT = 3 * JT * HP + 3 * JT * IP + 2 * BT * HP + 2 * BT * IP + 4 * JT + 2 * BT;
    for (int e = tid; e < SM_TOT; e += NTH) smem[e] = 0.f;
    __syncthreads();

    // weight tiles: per hidden unit jj, contiguous K array per gate (zero-padded)
    for (int e = tid; e < JT * H; e += NTH) {
        int jj = e / H, k = e % H;
        int j = j0 + jj;
        if (j < H) {
            sUz[jj * HP + k] = U[k * 3 * H + j];
            sUr[jj * HP + k] = U[k * 3 * H + H + j];
            sUh[jj * HP + k] = U[k * 3 * H + 2 * H + j];
        }
    }
    for (int e = tid; e < JT * I; e += NTH) {
        int jj = e / I, i = e % I;
        int j = j0 + jj;
        if (j < H) {
            sWz[jj * IP + i] = W[i * 3 * H + j];
            sWr[jj * IP + i] = W[i * 3 * H + H + j];
            sWh[jj * IP + i] = W[i * 3 * H + 2 * H + j];
        }
    }
    if (tid < JT) {
        int j = j0 + tid;
        if (j < H) {
            sbz[tid]  = bias[j] + bias[3 * H + j];
            sbr[tid]  = bias[H + j] + bias[3 * H + H + j];
            sbxh[tid] = bias[2 * H + j];
            sbrh[tid] = bias[3 * H + 2 * H + j];
        }
    }
    __syncthreads();

    // remote h-buffer bases for DSMEM broadcast
    uint32_t sh_local = smem_u32(sh);
    uint32_t rbase[GJ];
#pragma unroll
    for (int r = 0; r < GJ; r++) rbase[r] = mapa_shared(sh_local, (uint32_t)r);

    // stage x(0) + mask(0) into buffer 0
    for (int e = tid; e < BT * I; e += NTH) {
        int bb = e / I, i = e - bb * I;
        cp_async4(smem_u32(sx + bb * IP + i), in_seq + ((size_t)(b0 + bb) * TT) * I + i);
    }
    if (USEMASK && tid < BT)
        cp_async4(smem_u32(smk + tid), mask + (size_t)(b0 + tid) * TT);
    cp_commit();
    cp_wait0();
    cluster_sync_();

    // thread mapping: tid = item * KS + ks, item = b + BT * jj
    const int ksid = tid % KS;
    const int item = tid / KS;
    const int b  = item % BT;
    const int jj = item / BT;
    const int j  = j0 + jj;
    const bool active = (item < BT * JT) && (j < H);
    const unsigned lane = tid & 31u;
    const unsigned pm = ((1u << KS) - 1u) << (lane & ~(unsigned)(KS - 1));

    int p = 0;
    for (int t = 0; t < TT; t++) {
        const int cur = t & 1, nxt = cur ^ 1;
        // prefetch x(t+1) + mask(t+1)
        if (t + 1 < TT) {
            for (int e = tid; e < BT * I; e += NTH) {
                int bb = e / I, i = e - bb * I;
                cp_async4(smem_u32(sx + nxt * BT * IP + bb * IP + i),
                          in_seq + ((size_t)(b0 + bb) * TT + (t + 1)) * I + i);
            }
            if (USEMASK && tid < BT)
                cp_async4(smem_u32(smk + nxt * BT + tid),
                          mask + (size_t)(b0 + tid) * TT + (t + 1));
        }
        cp_commit();

        if (active) {
            unsigned long long az2 = 0ull, ar2 = 0ull, arh2 = 0ull, axh2 = 0ull;
            const float* hb  = sh + p * BT * HP + b * HP;
            const float* uzb = sUz + jj * HP;
            const float* urb = sUr + jj * HP;
            const float* uhb = sUh + jj * HP;
#pragma unroll 4
            for (int g = ksid; g < HPG; g += KS) {
                ulonglong2 h2 = *reinterpret_cast<const ulonglong2*>(hb  + 4 * g);
                ulonglong2 z2 = *reinterpret_cast<const ulonglong2*>(uzb + 4 * g);
                ulonglong2 r2 = *reinterpret_cast<const ulonglong2*>(urb + 4 * g);
                ulonglong2 g2 = *reinterpret_cast<const ulonglong2*>(uhb + 4 * g);
                ffma2(az2,  h2.x, z2.x); ffma2(az2,  h2.y, z2.y);
                ffma2(ar2,  h2.x, r2.x); ffma2(ar2,  h2.y, r2.y);
                ffma2(arh2, h2.x, g2.x); ffma2(arh2, h2.y, g2.y);
            }
            const float* xb  = sx + cur * BT * IP + b * IP;
            const float* wzb = sWz + jj * IP;
            const float* wrb = sWr + jj * IP;
            const float* whb = sWh + jj * IP;
#pragma unroll 4
            for (int g = ksid; g < IPG; g += KS) {
                ulonglong2 x2 = *reinterpret_cast<const ulonglong2*>(xb  + 4 * g);
                ulonglong2 z2 = *reinterpret_cast<const ulonglong2*>(wzb + 4 * g);
                ulonglong2 r2 = *reinterpret_cast<const ulonglong2*>(wrb + 4 * g);
                ulonglong2 g2 = *reinterpret_cast<const ulonglong2*>(whb + 4 * g);
                ffma2(az2,  x2.x, z2.x); ffma2(az2,  x2.y, z2.y);
                ffma2(ar2,  x2.x, r2.x); ffma2(ar2,  x2.y, r2.y);
                ffma2(axh2, x2.x, g2.x); ffma2(axh2, x2.y, g2.y);
            }

            // reduce over K-split lanes
            if (KS > 1) {
#pragma unroll
                for (int off = 1; off < KS; off <<= 1) {
                    az2  = addf2(az2,  __shfl_xor_sync(pm, az2,  off));
                    ar2  = addf2(ar2,  __shfl_xor_sync(pm, ar2,  off));
                    arh2 = addf2(arh2, __shfl_xor_sync(pm, arh2, off));
                    axh2 = addf2(axh2, __shfl_xor_sync(pm, axh2, off));
                }
            }

            if (ksid == 0) {
                float az  = hsum2(az2)  + sbz[jj];
                float ar  = hsum2(ar2)  + sbr[jj];
                float arh = hsum2(arh2) + sbrh[jj];
                float axh = hsum2(axh2) + sbxh[jj];
                float z = HARDSIG ? hsig(az) : sigm(az);
                float r = HARDSIG ? hsig(ar) : sigm(ar);
                float hh = axh + r * arh;
                if (TANHACT) hh = tanhf(hh);
                float hprev = sh[p * BT * HP + b * HP + j];
                float hn = z * hprev + (1.f - z) * hh;
                if (USEMASK) { if (smk[cur * BT + b] == 0.f) hn = hprev; }

                uint32_t off = (uint32_t)((((p ^ 1) * BT * HP) + b * HP + j) * 4);
#pragma unroll
                for (int r2i = 0; r2i < GJ; r2i++) st_cluster_f32(rbase[r2i] + off, hn);

                if (WRITESEQ) out_seq[((size_t)(b0 + b) * TT + t) * H + j] = hn;
            }
        }
        cp_wait0();
        cluster_sync_();
        p ^= 1;
    }

    if (!WRITESEQ) {
        if (active && ksid == 0) out_seq[(size_t)(b0 + b) * H + j] = sh[p * BT * HP + b * HP + j];
    }
}

// ===================== small kernels =====================
__global__ void mask_kernel(const float* __restrict__ x, float* __restrict__ m) {
    int idx = blockIdx.x * blockDim.x + threadIdx.x;
    if (idx < BB * TT) {
        float4 v = ((const float4*)x)[idx];
        m[idx] = (v.x != 0.f || v.y != 0.f || v.z != 0.f || v.w != 0.f) ? 1.f : 0.f;
    }
}

__global__ void combine34_kernel(const float* __restrict__ W3, const float* __restrict__ U3,
                                 const float* __restrict__ b3, const float* __restrict__ W4,
                                 const float* __restrict__ U4, const float* __restrict__ b4,
                                 float* __restrict__ Uc, float* __restrict__ Wc,
                                 float* __restrict__ bc) {
    const int NU = 60 * 180, NW = 150 * 180, NBc = 2 * 180;
    for (int e = blockIdx.x * blockDim.x + threadIdx.x; e < NU + NW + NBc;
         e += gridDim.x * blockDim.x) {
        if (e < NU) {
            int k = e / 180, col = e % 180;
            int g = col / 60, jj = col % 60;
            float v = 0.f;
            if (jj < 30) { if (k < 30)  v = U3[k * 90 + g * 30 + jj]; }
            else         { if (k >= 30) v = U4[(k - 30) * 90 + g * 30 + (jj - 30)]; }
            Uc[e] = v;
        } else if (e < NU + NW) {
            int e2 = e - NU;
            int i = e2 / 180, col = e2 % 180;
            int g = col / 60, jj = col % 60;
            Wc[e2] = (jj < 30) ? W3[i * 90 + g * 30 + jj] : W4[i * 90 + g * 30 + (jj - 30)];
        } else {
            int e2 = e - NU - NW;
            int rr = e2 / 180, col = e2 % 180;
            int g = col / 60, jj = col % 60;
            bc[e2] = (jj < 30) ? b3[rr * 90 + g * 30 + jj] : b4[rr * 90 + g * 30 + (jj - 30)];
        }
    }
}

__global__ void z_kernel(const float* __restrict__ h34, const float* __restrict__ eps,
                         float* __restrict__ z) {
    int idx = blockIdx.x * blockDim.x + threadIdx.x;
    if (idx < BB * 30) {
        int b = idx / 30, c = idx % 30;
        z[idx] = h34[b * 60 + c] + expf(0.5f * h34[b * 60 + 30 + c]) * eps[idx];
    }
}

__global__ void decin_kernel(const float* __restrict__ z, const float* __restrict__ tin2,
                             const float* __restrict__ masks, float* __restrict__ dec_in) {
    const size_t N = (size_t)BB * TT * 32;
    for (size_t idx = (size_t)blockIdx.x * blockDim.x + threadIdx.x; idx < N;
         idx += (size_t)gridDim.x * blockDim.x) {
        size_t b = idx / ((size_t)TT * 32);
        size_t rem = idx % ((size_t)TT * 32);
        size_t t = rem / 32;
        int c = (int)(rem % 32);
        float v = (c < 30) ? z[b * 30 + c] : tin2[(b * TT + t) * 2 + (c - 30)];
        dec_in[idx] = v * masks[idx];
    }
}

__global__ void dense_kernel(const float* __restrict__ h6, const float* __restrict__ Wd,
                             const float* __restrict__ bd, const float* __restrict__ dec_masks,
                             float* __restrict__ out) {
    int gtid = blockIdx.x * blockDim.x + threadIdx.x;
    int row = gtid >> 5;
    int lane = gtid & 31;
    if (row >= BB * TT) return;
    float s = 0.f;
    const float* hrow = h6 + (size_t)row * 175;
    for (int k = lane; k < 175; k += 32) s = fmaf(hrow[k], Wd[k], s);
#pragma unroll
    for (int off = 16; off; off >>= 1) s += __shfl_down_sync(0xffffffffu, s, off);
    if (lane == 0) out[row] = tanhf(s + bd[0]) * dec_masks[row];
}

// ===================== host-side launch helper =====================
template <int H, int I, int KS, int NTH, bool HARDSIG, bool TANHACT, bool USEMASK, bool WRITESEQ>
static void launch_gru(const float* in_seq, const float* U, const float* W, const float* bias,
                       const float* mask, float* out_seq) {
    constexpr int JT = (H + 7) / 8;
    constexpr int HP = padDim(H), IP = padDim(I);
    constexpr int SM_TOT = 3 * JT * HP + 3 * JT * IP + 2 * 8 * HP + 2 * 8 * IP + 4 * JT + 16;
    constexpr int smem_bytes = SM_TOT * 4;
    cudaFuncSetAttribute(gru_kernel<H, I, KS, NTH, HARDSIG, TANHACT, USEMASK, WRITESEQ>,
                         cudaFuncAttributeMaxDynamicSharedMemorySize, smem_bytes);
    gru_kernel<H, I, KS, NTH, HARDSIG, TANHACT, USEMASK, WRITESEQ>
        <<<128, NTH, smem_bytes>>>(in_seq, U, W, bias, mask, out_seq);
}

extern "C" void kernel_launch(void* const* d_in, const int* in_sizes, int n_in,
                              void* d_out, int out_size) {
    const float* x         = (const float*)d_in[0];
    const float* tin2      = (const float*)d_in[1];
    const float* masks     = (const float*)d_in[2];
    const float* dec_masks = (const float*)d_in[3];
    const float* eps       = (const float*)d_in[4];
    const float* W1 = (const float*)d_in[5];
    const float* U1 = (const float*)d_in[6];
    const float* b1 = (const float*)d_in[7];
    const float* W2 = (const float*)d_in[8];
    const float* U2 = (const float*)d_in[9];
    const float* b2 = (const float*)d_in[10];
    const float* W3 = (const float*)d_in[11];
    const float* U3 = (const float*)d_in[12];
    const float* b3 = (const float*)d_in[13];
    const float* W4 = (const float*)d_in[14];
    const float* U4 = (const float*)d_in[15];
    const float* b4 = (const float*)d_in[16];
    const float* W5 = (const float*)d_in[17];
    const float* U5 = (const float*)d_in[18];
    const float* b5 = (const float*)d_in[19];
    const float* W6 = (const float*)d_in[20];
    const float* U6 = (const float*)d_in[21];
    const float* b6 = (const float*)d_in[22];
    const float* Wd = (const float*)d_in[23];
    const float* bd = (const float*)d_in[24];
    float* out = (float*)d_out;

    void *pA, *pB, *pM, *pH34, *pZ, *pUc, *pWc, *pBc;
    cudaGetSymbolAddress(&pA, g_bufA);
    cudaGetSymbolAddress(&pB, g_bufB);
    cudaGetSymbolAddress(&pM, g_mask);
    cudaGetSymbolAddress(&pH34, g_h34);
    cudaGetSymbolAddress(&pZ, g_z);
    cudaGetSymbolAddress(&pUc, g_Uc);
    cudaGetSymbolAddress(&pWc, g_Wc);
    cudaGetSymbolAddress(&pBc, g_bc);
    float* bufA = (float*)pA;
    float* bufB = (float*)pB;
    float* mptr = (float*)pM;
    float* h34  = (float*)pH34;
    float* zbuf = (float*)pZ;
    float* Uc   = (float*)pUc;
    float* Wc   = (float*)pWc;
    float* Bc   = (float*)pBc;

    // prep kernels
    mask_kernel<<<(BB * TT + 255) / 256, 256>>>(x, mptr);
    combine34_kernel<<<64, 256>>>(W3, U3, b3, W4, U4, b4, Uc, Wc, Bc);

    // encoder GRU1 (H=175, I=4): KS=2, 352 threads
    launch_gru<175, 4, 2, 352, true, true, true, true>(x, U1, W1, b1, mptr, bufA);

    // encoder GRU2 (H=150, I=175): KS=2, 320 threads
    launch_gru<150, 175, 2, 320, true, true, true, true>(bufA, U2, W2, b2, mptr, bufB);

    // fused GRU3+GRU4 (H=60, I=150): KS=4, 256 threads, final state only
    launch_gru<60, 150, 4, 256, false, false, true, false>(bufB, Uc, Wc, Bc, mptr, h34);

    // reparameterize + decoder input
    z_kernel<<<(BB * 30 + 255) / 256, 256>>>(h34, eps, zbuf);
    decin_kernel<<<1024, 256>>>(zbuf, tin2, masks, bufA);

    // decoder GRU5 (H=150, I=32): KS=2, 320 threads
    launch_gru<150, 32, 2, 320, true, true, false, true>(bufA, U5, W5, b5, nullptr, bufB);

    // decoder GRU6 (H=175, I=150): KS=2, 352 threads
    launch_gru<175, 150, 2, 352, true, true, false, true>(bufB, U6, W6, b6, nullptr, bufA);

    // dense head + output mask
    dense_kernel<<<(BB * TT + 7) / 8, 256>>>(bufA, Wd, bd, dec_masks, out);
}

// round 3
// speedup vs baseline: 1.0006x; 1.0006x over previous
#include <cuda_runtime.h>
#include <cstdint>
#include <cstdio>

// ===================== problem constants =====================
#define BB 128
#define TT 2048

// ===================== static device scratch =====================
__device__ float g_bufA[(size_t)BB * TT * 175];
__device__ float g_bufB[(size_t)BB * TT * 175];
__device__ float g_mask[(size_t)BB * TT];
__device__ float g_h34[BB * 60];
__device__ float g_z[BB * 30];
__device__ float g_Uc[60 * 180];
__device__ float g_Wc[150 * 180];
__device__ float g_bc[2 * 180];

// ===================== helpers =====================
__host__ __device__ constexpr int padDim(int v) {
    int h = (v + 3) / 4 * 4;
    if (((h / 4) & 1) == 0) h += 4;   // (h/4) odd -> conflict-free 8-way float4 strides
    return h;
}

__device__ __forceinline__ uint32_t smem_u32(const void* p) {
    uint32_t a;
    asm("{ .reg .u64 t; cvta.to.shared.u64 t, %1; cvt.u32.u64 %0, t; }" : "=r"(a) : "l"(p));
    return a;
}
__device__ __forceinline__ uint32_t mapa_shared(uint32_t local, uint32_t rank) {
    uint32_t r;
    asm("mapa.shared::cluster.u32 %0, %1, %2;" : "=r"(r) : "r"(local), "r"(rank));
    return r;
}
__device__ __forceinline__ void st_cluster_f32(uint32_t addr, float v) {
    asm volatile("st.shared::cluster.b32 [%0], %1;" :: "r"(addr), "r"(__float_as_uint(v)));
}
__device__ __forceinline__ void cluster_sync_() {
    asm volatile("barrier.cluster.arrive.aligned;" ::: "memory");
    asm volatile("barrier.cluster.wait.aligned;" ::: "memory");
}
__device__ __forceinline__ void cp_async4(uint32_t dst, const void* src) {
    asm volatile("cp.async.ca.shared.global [%0], [%1], 4;" :: "r"(dst), "l"(src));
}
__device__ __forceinline__ void cp_commit() {
    asm volatile("cp.async.commit_group;" ::: "memory");
}
__device__ __forceinline__ void cp_wait0() {
    asm volatile("cp.async.wait_group 0;" ::: "memory");
}

// packed f32x2 ops (Blackwell)
__device__ __forceinline__ void ffma2(unsigned long long &c, unsigned long long a,
                                      unsigned long long b) {
    asm("fma.rn.f32x2 %0, %1, %2, %3;" : "=l"(c) : "l"(a), "l"(b), "l"(c));
}
__device__ __forceinline__ unsigned long long addf2(unsigned long long a, unsigned long long b) {
    unsigned long long c;
    asm("add.rn.f32x2 %0, %1, %2;" : "=l"(c) : "l"(a), "l"(b));
    return c;
}
__device__ __forceinline__ float hsum2(unsigned long long v) {
    float a, b;
    asm("mov.b64 {%0,%1}, %2;" : "=f"(a), "=f"(b) : "l"(v));
    return a + b;
}

__device__ __forceinline__ float hsig(float v) { return fminf(fmaxf(0.2f * v + 0.5f, 0.f), 1.f); }
__device__ __forceinline__ float sigm(float v) { return 1.f / (1.f + expf(-v)); }

// ===================== persistent GRU kernel =====================
// Cluster of 8 CTAs = 8 batch rows; CTA r owns hidden tile r (JT units).
// Thread = (ks, b, jj): K dimension split KS ways, reduced via warp shfl.
// Packed f32x2 FMAs along K (2 MACs/instr). x_{t+1} prefetched via cp.async.
// One cluster barrier per step; h exchanged via DSMEM stores.
template <int H, int I, int KS, int NTH, bool HARDSIG, bool TANHACT, bool USEMASK, bool WRITESEQ>
__global__ void __cluster_dims__(8, 1, 1) __launch_bounds__(NTH, 1)
gru_kernel(const float* __restrict__ in_seq, const float* __restrict__ U,
           const float* __restrict__ W, const float* __restrict__ bias,
           const float* __restrict__ mask, float* __restrict__ out_seq)
{
    constexpr int GJ = 8, BT = 8;
    constexpr int JT = (H + GJ - 1) / GJ;
    constexpr int HP = padDim(H), IP = padDim(I);
    constexpr int HPG = HP / 4, IPG = IP / 4;
    static_assert(BT * JT * KS <= NTH, "thread budget");

    extern __shared__ float smem[];
    float* sUz = smem;
    float* sUr = sUz + JT * HP;
    float* sUh = sUr + JT * HP;
    float* sWz = sUh + JT * HP;
    float* sWr = sWz + JT * IP;
    float* sWh = sWr + JT * IP;
    float* sh  = sWh + JT * IP;          // 2 * BT * HP (double buffer)
    float* sx  = sh  + 2 * BT * HP;      // 2 * BT * IP (double buffer)
    float* sbz = sx  + 2 * BT * IP;
    float* sbr = sbz + JT;
    float* sbxh = sbr + JT;
    float* sbrh = sbxh + JT;
    float* smk  = sbrh + JT;             // 2 * BT

    const int tid  = threadIdx.x;
    const int rank = blockIdx.x & 7;
    const int ci   = blockIdx.x >> 3;
    const int b0   = ci * BT;
    const int j0   = rank * JT;

    constexpr int SM_TOT = 3 * JT * HP + 3 * JT * IP + 2 * BT * HP + 2 * BT * IP + 4 * JT + 2 * BT;
    for (int e = tid; e < SM_TOT; e += NTH) smem[e] = 0.f;
    __syncthreads();

    // weight tiles: per hidden unit jj, contiguous K array per gate (zero-padded)
    for (int e = tid; e < JT * H; e += NTH) {
        int jj = e / H, k = e % H;
        int j = j0 + jj;
        if (j < H) {
            sUz[jj * HP + k] = U[k * 3 * H + j];
            sUr[jj * HP + k] = U[k * 3 * H + H + j];
            sUh[jj * HP + k] = U[k * 3 * H + 2 * H + j];
        }
    }
    for (int e = tid; e < JT * I; e += NTH) {
        int jj = e / I, i = e % I;
        int j = j0 + jj;
        if (j < H) {
            sWz[jj * IP + i] = W[i * 3 * H + j];
            sWr[jj * IP + i] = W[i * 3 * H + H + j];
            sWh[jj * IP + i] = W[i * 3 * H + 2 * H + j];
        }
    }
    if (tid < JT) {
        int j = j0 + tid;
        if (j < H) {
            sbz[tid]  = bias[j] + bias[3 * H + j];
            sbr[tid]  = bias[H + j] + bias[3 * H + H + j];
            sbxh[tid] = bias[2 * H + j];
            sbrh[tid] = bias[3 * H + 2 * H + j];
        }
    }
    __syncthreads();

    // remote h-buffer bases for DSMEM broadcast
    uint32_t sh_local = smem_u32(sh);
    uint32_t rbase[GJ];
#pragma unroll
    for (int r = 0; r < GJ; r++) rbase[r] = mapa_shared(sh_local, (uint32_t)r);

    // stage x(0) + mask(0) into buffer 0
    for (int e = tid; e < BT * I; e += NTH) {
        int bb = e / I, i = e - bb * I;
        cp_async4(smem_u32(sx + bb * IP + i), in_seq + ((size_t)(b0 + bb) * TT) * I + i);
    }
    if (USEMASK && tid < BT)
        cp_async4(smem_u32(smk + tid), mask + (size_t)(b0 + tid) * TT);
    cp_commit();
    cp_wait0();
    cluster_sync_();

    // thread mapping: tid = item * KS + ks, item = b + BT * jj
    const int ksid = tid % KS;
    const int item = tid / KS;
    const int b  = item % BT;
    const int jj = item / BT;
    const int j  = j0 + jj;
    const bool active = (item < BT * JT) && (j < H);
    const unsigned lane = tid & 31u;
    const unsigned pm = ((1u << KS) - 1u) << (lane & ~(unsigned)(KS - 1));

    int p = 0;
    for (int t = 0; t < TT; t++) {
        const int cur = t & 1, nxt = cur ^ 1;
        // prefetch x(t+1) + mask(t+1)
        if (t + 1 < TT) {
            for (int e = tid; e < BT * I; e += NTH) {
                int bb = e / I, i = e - bb * I;
                cp_async4(smem_u32(sx + nxt * BT * IP + bb * IP + i),
                          in_seq + ((size_t)(b0 + bb) * TT + (t + 1)) * I + i);
            }
            if (USEMASK && tid < BT)
                cp_async4(smem_u32(smk + nxt * BT + tid),
                          mask + (size_t)(b0 + tid) * TT + (t + 1));
        }
        cp_commit();

        if (active) {
            unsigned long long az2 = 0ull, ar2 = 0ull, arh2 = 0ull, axh2 = 0ull;
            const float* hb  = sh + p * BT * HP + b * HP;
            const float* uzb = sUz + jj * HP;
            const float* urb = sUr + jj * HP;
            const float* uhb = sUh + jj * HP;
#pragma unroll 4
            for (int g = ksid; g < HPG; g += KS) {
                ulonglong2 h2 = *reinterpret_cast<const ulonglong2*>(hb  + 4 * g);
                ulonglong2 z2 = *reinterpret_cast<const ulonglong2*>(uzb + 4 * g);
                ulonglong2 r2 = *reinterpret_cast<const ulonglong2*>(urb + 4 * g);
                ulonglong2 g2 = *reinterpret_cast<const ulonglong2*>(uhb + 4 * g);
                ffma2(az2,  h2.x, z2.x); ffma2(az2,  h2.y, z2.y);
                ffma2(ar2,  h2.x, r2.x); ffma2(ar2,  h2.y, r2.y);
                ffma2(arh2, h2.x, g2.x); ffma2(arh2, h2.y, g2.y);
            }
            const float* xb  = sx + cur * BT * IP + b * IP;
            const float* wzb = sWz + jj * IP;
            const float* wrb = sWr + jj * IP;
            const float* whb = sWh + jj * IP;
#pragma unroll 4
            for (int g = ksid; g < IPG; g += KS) {
                ulonglong2 x2 = *reinterpret_cast<const ulonglong2*>(xb  + 4 * g);
                ulonglong2 z2 = *reinterpret_cast<const ulonglong2*>(wzb + 4 * g);
                ulonglong2 r2 = *reinterpret_cast<const ulonglong2*>(wrb + 4 * g);
                ulonglong2 g2 = *reinterpret_cast<const ulonglong2*>(whb + 4 * g);
                ffma2(az2,  x2.x, z2.x); ffma2(az2,  x2.y, z2.y);
                ffma2(ar2,  x2.x, r2.x); ffma2(ar2,  x2.y, r2.y);
                ffma2(axh2, x2.x, g2.x); ffma2(axh2, x2.y, g2.y);
            }

            // reduce over K-split lanes
            if (KS > 1) {
#pragma unroll
                for (int off = 1; off < KS; off <<= 1) {
                    az2  = addf2(az2,  __shfl_xor_sync(pm, az2,  off));
                    ar2  = addf2(ar2,  __shfl_xor_sync(pm, ar2,  off));
                    arh2 = addf2(arh2, __shfl_xor_sync(pm, arh2, off));
                    axh2 = addf2(axh2, __shfl_xor_sync(pm, axh2, off));
                }
            }

            if (ksid == 0) {
                float az  = hsum2(az2)  + sbz[jj];
                float ar  = hsum2(ar2)  + sbr[jj];
                float arh = hsum2(arh2) + sbrh[jj];
                float axh = hsum2(axh2) + sbxh[jj];
                float z = HARDSIG ? hsig(az) : sigm(az);
                float r = HARDSIG ? hsig(ar) : sigm(ar);
                float hh = axh + r * arh;
                if (TANHACT) hh = tanhf(hh);
                float hprev = sh[p * BT * HP + b * HP + j];
                float hn = z * hprev + (1.f - z) * hh;
                if (USEMASK) { if (smk[cur * BT + b] == 0.f) hn = hprev; }

                uint32_t off = (uint32_t)((((p ^ 1) * BT * HP) + b * HP + j) * 4);
#pragma unroll
                for (int r2i = 0; r2i < GJ; r2i++) st_cluster_f32(rbase[r2i] + off, hn);

                if (WRITESEQ) out_seq[((size_t)(b0 + b) * TT + t) * H + j] = hn;
            }
        }
        cp_wait0();
        cluster_sync_();
        p ^= 1;
    }

    if (!WRITESEQ) {
        if (active && ksid == 0) out_seq[(size_t)(b0 + b) * H + j] = sh[p * BT * HP + b * HP + j];
    }
}

// ===================== small kernels =====================
__global__ void mask_kernel(const float* __restrict__ x, float* __restrict__ m) {
    int idx = blockIdx.x * blockDim.x + threadIdx.x;
    if (idx < BB * TT) {
        float4 v = ((const float4*)x)[idx];
        m[idx] = (v.x != 0.f || v.y != 0.f || v.z != 0.f || v.w != 0.f) ? 1.f : 0.f;
    }
}

__global__ void combine34_kernel(const float* __restrict__ W3, const float* __restrict__ U3,
                                 const float* __restrict__ b3, const float* __restrict__ W4,
                                 const float* __restrict__ U4, const float* __restrict__ b4,
                                 float* __restrict__ Uc, float* __restrict__ Wc,
                                 float* __restrict__ bc) {
    const int NU = 60 * 180, NW = 150 * 180, NBc = 2 * 180;
    for (int e = blockIdx.x * blockDim.x + threadIdx.x; e < NU + NW + NBc;
         e += gridDim.x * blockDim.x) {
        if (e < NU) {
            int k = e / 180, col = e % 180;
            int g = col / 60, jj = col % 60;
            float v = 0.f;
            if (jj < 30) { if (k < 30)  v = U3[k * 90 + g * 30 + jj]; }
            else         { if (k >= 30) v = U4[(k - 30) * 90 + g * 30 + (jj - 30)]; }
            Uc[e] = v;
        } else if (e < NU + NW) {
            int e2 = e - NU;
            int i = e2 / 180, col = e2 % 180;
            int g = col / 60, jj = col % 60;
            Wc[e2] = (jj < 30) ? W3[i * 90 + g * 30 + jj] : W4[i * 90 + g * 30 + (jj - 30)];
        } else {
            int e2 = e - NU - NW;
            int rr = e2 / 180, col = e2 % 180;
            int g = col / 60, jj = col % 60;
            bc[e2] = (jj < 30) ? b3[rr * 90 + g * 30 + jj] : b4[rr * 90 + g * 30 + (jj - 30)];
        }
    }
}

__global__ void z_kernel(const float* __restrict__ h34, const float* __restrict__ eps,
                         float* __restrict__ z) {
    int idx = blockIdx.x * blockDim.x + threadIdx.x;
    if (idx < BB * 30) {
        int b = idx / 30, c = idx % 30;
        z[idx] = h34[b * 60 + c] + expf(0.5f * h34[b * 60 + 30 + c]) * eps[idx];
    }
}

__global__ void decin_kernel(const float* __restrict__ z, const float* __restrict__ tin2,
                             const float* __restrict__ masks, float* __restrict__ dec_in) {
    const size_t N = (size_t)BB * TT * 32;
    for (size_t idx = (size_t)blockIdx.x * blockDim.x + threadIdx.x; idx < N;
         idx += (size_t)gridDim.x * blockDim.x) {
        size_t b = idx / ((size_t)TT * 32);
        size_t rem = idx % ((size_t)TT * 32);
        size_t t = rem / 32;
        int c = (int)(rem % 32);
        float v = (c < 30) ? z[b * 30 + c] : tin2[(b * TT + t) * 2 + (c - 30)];
        dec_in[idx] = v * masks[idx];
    }
}

__global__ void dense_kernel(const float* __restrict__ h6, const float* __restrict__ Wd,
                             const float* __restrict__ bd, const float* __restrict__ dec_masks,
                             float* __restrict__ out) {
    int gtid = blockIdx.x * blockDim.x + threadIdx.x;
    int row = gtid >> 5;
    int lane = gtid & 31;
    if (row >= BB * TT) return;
    float s = 0.f;
    const float* hrow = h6 + (size_t)row * 175;
    for (int k = lane; k < 175; k += 32) s = fmaf(hrow[k], Wd[k], s);
#pragma unroll
    for (int off = 16; off; off >>= 1) s += __shfl_down_sync(0xffffffffu, s, off);
    if (lane == 0) out[row] = tanhf(s + bd[0]) * dec_masks[row];
}

// ===================== host-side launch helper =====================
template <int H, int I, int KS, int NTH, bool HARDSIG, bool TANHACT, bool USEMASK, bool WRITESEQ>
static void launch_gru(const float* in_seq, const float* U, const float* W, const float* bias,
                       const float* mask, float* out_seq) {
    constexpr int JT = (H + 7) / 8;
    constexpr int HP = padDim(H), IP = padDim(I);
    constexpr int SM_TOT = 3 * JT * HP + 3 * JT * IP + 2 * 8 * HP + 2 * 8 * IP + 4 * JT + 16;
    constexpr int smem_bytes = SM_TOT * 4;
    cudaFuncSetAttribute(gru_kernel<H, I, KS, NTH, HARDSIG, TANHACT, USEMASK, WRITESEQ>,
                         cudaFuncAttributeMaxDynamicSharedMemorySize, smem_bytes);
    gru_kernel<H, I, KS, NTH, HARDSIG, TANHACT, USEMASK, WRITESEQ>
        <<<128, NTH, smem_bytes>>>(in_seq, U, W, bias, mask, out_seq);
}

extern "C" void kernel_launch(void* const* d_in, const int* in_sizes, int n_in,
                              void* d_out, int out_size) {
    const float* x         = (const float*)d_in[0];
    const float* tin2      = (const float*)d_in[1];
    const float* masks     = (const float*)d_in[2];
    const float* dec_masks = (const float*)d_in[3];
    const float* eps       = (const float*)d_in[4];
    const float* W1 = (const float*)d_in[5];
    const float* U1 = (const float*)d_in[6];
    const float* b1 = (const float*)d_in[7];
    const float* W2 = (const float*)d_in[8];
    const float* U2 = (const float*)d_in[9];
    const float* b2 = (const float*)d_in[10];
    const float* W3 = (const float*)d_in[11];
    const float* U3 = (const float*)d_in[12];
    const float* b3 = (const float*)d_in[13];
    const float* W4 = (const float*)d_in[14];
    const float* U4 = (const float*)d_in[15];
    const float* b4 = (const float*)d_in[16];
    const float* W5 = (const float*)d_in[17];
    const float* U5 = (const float*)d_in[18];
    const float* b5 = (const float*)d_in[19];
    const float* W6 = (const float*)d_in[20];
    const float* U6 = (const float*)d_in[21];
    const float* b6 = (const float*)d_in[22];
    const float* Wd = (const float*)d_in[23];
    const float* bd = (const float*)d_in[24];
    float* out = (float*)d_out;

    void *pA, *pB, *pM, *pH34, *pZ, *pUc, *pWc, *pBc;
    cudaGetSymbolAddress(&pA, g_bufA);
    cudaGetSymbolAddress(&pB, g_bufB);
    cudaGetSymbolAddress(&pM, g_mask);
    cudaGetSymbolAddress(&pH34, g_h34);
    cudaGetSymbolAddress(&pZ, g_z);
    cudaGetSymbolAddress(&pUc, g_Uc);
    cudaGetSymbolAddress(&pWc, g_Wc);
    cudaGetSymbolAddress(&pBc, g_bc);
    float* bufA = (float*)pA;
    float* bufB = (float*)pB;
    float* mptr = (float*)pM;
    float* h34  = (float*)pH34;
    float* zbuf = (float*)pZ;
    float* Uc   = (float*)pUc;
    float* Wc   = (float*)pWc;
    float* Bc   = (float*)pBc;

    // prep kernels
    mask_kernel<<<(BB * TT + 255) / 256, 256>>>(x, mptr);
    combine34_kernel<<<64, 256>>>(W3, U3, b3, W4, U4, b4, Uc, Wc, Bc);

    // encoder GRU1 (H=175, I=4): KS=2, 352 threads
    launch_gru<175, 4, 2, 352, true, true, true, true>(x, U1, W1, b1, mptr, bufA);

    // encoder GRU2 (H=150, I=175): KS=2, 320 threads
    launch_gru<150, 175, 2, 320, true, true, true, true>(bufA, U2, W2, b2, mptr, bufB);

    // fused GRU3+GRU4 (H=60, I=150): KS=4, 256 threads, final state only
    launch_gru<60, 150, 4, 256, false, false, true, false>(bufB, Uc, Wc, Bc, mptr, h34);

    // reparameterize + decoder input
    z_kernel<<<(BB * 30 + 255) / 256, 256>>>(h34, eps, zbuf);
    decin_kernel<<<1024, 256>>>(zbuf, tin2, masks, bufA);

    // decoder GRU5 (H=150, I=32): KS=2, 320 threads
    launch_gru<150, 32, 2, 320, true, true, false, true>(bufA, U5, W5, b5, nullptr, bufB);

    // decoder GRU6 (H=175, I=150): KS=2, 352 threads
    launch_gru<175, 150, 2, 352, true, true, false, true>(bufB, U6, W6, b6, nullptr, bufA);

    // dense head + output mask
    dense_kernel<<<(BB * TT + 7) / 8, 256>>>(bufA, Wd, bd, dec_masks, out);
}

// round 4
// speedup vs baseline: 1.2669x; 1.2661x over previous
#include <cuda_runtime.h>
#include <cstdint>
#include <cstdio>

// ===================== problem constants =====================
#define BB 128
#define TT 2048

// ===================== static device scratch =====================
// Padded-stride sequence buffers (stride = padDim(channels), max 180).
__device__ float g_bufA[(size_t)BB * TT * 180];
__device__ float g_bufB[(size_t)BB * TT * 180];
__device__ float g_mask[(size_t)BB * TT];
__device__ float g_h34[BB * 60];
__device__ float g_z[BB * 30];
__device__ float g_Uc[60 * 180];
__device__ float g_Wc[150 * 180];
__device__ float g_bc[2 * 180];

// ===================== helpers =====================
__host__ __device__ constexpr int padDim(int v) {
    int h = (v + 3) / 4 * 4;
    if (((h / 4) & 1) == 0) h += 4;
    return h;
}

__device__ __forceinline__ uint32_t smem_u32(const void* p) {
    uint32_t a;
    asm("{ .reg .u64 t; cvta.to.shared.u64 t, %1; cvt.u32.u64 %0, t; }" : "=r"(a) : "l"(p));
    return a;
}
__device__ __forceinline__ uint32_t mapa_shared(uint32_t local, uint32_t rank) {
    uint32_t r;
    asm("mapa.shared::cluster.u32 %0, %1, %2;" : "=r"(r) : "r"(local), "r"(rank));
    return r;
}
__device__ __forceinline__ void st_cluster_f32(uint32_t addr, float v) {
    asm volatile("st.shared::cluster.b32 [%0], %1;" :: "r"(addr), "r"(__float_as_uint(v)));
}
__device__ __forceinline__ void cluster_sync_() {
    asm volatile("barrier.cluster.arrive.aligned;" ::: "memory");
    asm volatile("barrier.cluster.wait.aligned;" ::: "memory");
}
__device__ __forceinline__ void cp_async16(uint32_t dst, const void* src) {
    asm volatile("cp.async.cg.shared.global [%0], [%1], 16;" :: "r"(dst), "l"(src));
}
__device__ __forceinline__ void cp_async4(uint32_t dst, const void* src) {
    asm volatile("cp.async.ca.shared.global [%0], [%1], 4;" :: "r"(dst), "l"(src));
}
__device__ __forceinline__ void cp_commit() {
    asm volatile("cp.async.commit_group;" ::: "memory");
}
__device__ __forceinline__ void cp_wait0() {
    asm volatile("cp.async.wait_group 0;" ::: "memory");
}

__device__ __forceinline__ float hsig(float v) { return fminf(fmaxf(0.2f * v + 0.5f, 0.f), 1.f); }
__device__ __forceinline__ float sigm(float v) { return 1.f / (1.f + expf(-v)); }

// ===================== persistent GRU kernel (register-tiled) =====================
// Cluster of 8 CTAs = 8 batch rows; CTA rank owns hidden tile [j0, j0+JT).
// One WARP owns (all 8 b) x (JJT hidden units); lanes split K (quads) 32 ways.
// Combined vector v[b] = [h (HP) | x (IP)]; weight rows concatenated likewise.
// Splitting-butterfly shfl reduction -> smem stage -> epilogue gates -> DSMEM bcast.
template <int H, int I, int JJT, int NTH, bool HSIG, bool TANHA, bool UM, bool WSEQ>
__global__ void __cluster_dims__(8, 1, 1) __launch_bounds__(NTH, 1)
gru_kernel(const float* __restrict__ in_seq, const float* __restrict__ U,
           const float* __restrict__ W, const float* __restrict__ bias,
           const float* __restrict__ mask, float* __restrict__ out_seq)
{
    constexpr int HP = padDim(H), IP = padDim(I), KP = HP + IP;
    constexpr int Q = KP / 4, HQ = HP / 4;
    constexpr int JT = (H + 7) / 8;
    constexpr int JG = (JT + JJT - 1) / JJT;
    constexpr int JTp = JG * JJT;
    constexpr int AC = 8 * JJT * 4;          // accumulators per warp (64 or 32)
    constexpr int H3 = 3 * H;
    static_assert(NTH == 32 * JG, "threads = 32 per jj-group");

    extern __shared__ float smem[];
    float* sW     = smem;                       // JTp*3*KP  (rows zero-padded)
    float* sv     = sW + JTp * 3 * KP;          // 2*8*KP    (double-buffered [h|x])
    float* sstage = sv + 2 * 8 * KP;            // JG*AC
    float* sbz    = sstage + JG * AC;           // JTp
    float* sbr    = sbz + JTp;
    float* sbrh   = sbr + JTp;
    float* sbxh   = sbrh + JTp;
    float* smk    = sbxh + JTp;                 // 2*8
    constexpr int SMTOT = JTp * 3 * KP + 16 * KP + JG * AC + 4 * JTp + 16;

    const int tid  = threadIdx.x;
    const int rank = blockIdx.x & 7;
    const int ci   = blockIdx.x >> 3;
    const int b0   = ci * 8;
    const int j0   = rank * JT;

    for (int e = tid; e < SMTOT; e += NTH) smem[e] = 0.f;
    __syncthreads();

    // ---- fill weights: row (jj,g) = [U[:,g*H+j] over k<H | W[:,g*H+j] over i<I], zero-padded
    for (int e = tid; e < JT * 3 * KP; e += NTH) {
        int jj = e / (3 * KP);
        int r  = e - jj * (3 * KP);
        int g  = r / KP;
        int k  = r - g * KP;
        int j  = j0 + jj;
        float val = 0.f;
        if (j < H) {
            if (k < HP) { if (k < H) val = U[k * H3 + g * H + j]; }
            else { int i = k - HP; if (i < I) val = W[i * H3 + g * H + j]; }
        }
        sW[(jj * 3 + g) * KP + k] = val;
    }
    if (tid < JT) {
        int j = j0 + tid;
        if (j < H) {
            sbz[tid]  = bias[j] + bias[H3 + j];
            sbr[tid]  = bias[H + j] + bias[H3 + H + j];
            sbxh[tid] = bias[2 * H + j];
            sbrh[tid] = bias[H3 + 2 * H + j];
        }
    }
    __syncthreads();

    const uint32_t svu = smem_u32(sv);
    uint32_t rb[8];
#pragma unroll
    for (int r = 0; r < 8; r++) rb[r] = mapa_shared(svu, (uint32_t)r);

    // ---- stage x(0), mask(0) into phase 0
    constexpr int XOPS = 8 * (IP / 4);
    {
        for (int e = tid; e < XOPS; e += NTH) {
            int bb = e / (IP / 4), i4 = e - bb * (IP / 4);
            cp_async16(svu + (uint32_t)((bb * KP + HP + i4 * 4) * 4),
                       in_seq + ((size_t)(b0 + bb) * TT) * IP + i4 * 4);
        }
        if (UM && tid < 8)
            cp_async4(smem_u32(smk + tid), mask + (size_t)(b0 + tid) * TT);
    }
    cp_commit();
    cp_wait0();
    cluster_sync_();

    const int w = tid >> 5, lane = tid & 31;
    // butterfly ownership index (bit-permutation of lane)
    int a0;
    if (AC == 64)
        a0 = ((lane & 1) << 5) | ((lane & 2) << 3) | ((lane & 4) << 1) |
             ((lane & 8) >> 1) | ((lane & 16) >> 3);
    else
        a0 = ((lane & 1) << 4) | ((lane & 2) << 2) | (lane & 4) |
             ((lane & 8) >> 2) | ((lane & 16) >> 4);

    int p = 0;
    for (int t = 0; t < TT; t++) {
        const int nxt = 1 - p;
        // ---- prefetch x(t+1), mask(t+1) into phase nxt
        if (t + 1 < TT) {
            for (int e = tid; e < XOPS; e += NTH) {
                int bb = e / (IP / 4), i4 = e - bb * (IP / 4);
                cp_async16(svu + (uint32_t)(((nxt * 8 + bb) * KP + HP + i4 * 4) * 4),
                           in_seq + ((size_t)(b0 + bb) * TT + (t + 1)) * IP + i4 * 4);
            }
            if (UM && tid < 8)
                cp_async4(smem_u32(smk + nxt * 8 + tid),
                          mask + (size_t)(b0 + tid) * TT + (t + 1));
        }
        cp_commit();

        // ---- main accumulation: warp covers 8 b x JJT units, lanes stride quads
        const float* vc = sv + p * 8 * KP;
        float accf[AC];
#pragma unroll
        for (int a = 0; a < AC; a++) accf[a] = 0.f;

        for (int g4 = lane; g4 < Q; g4 += 32) {
            const float* vq = vc + g4 * 4;
            float4 vb[8];
#pragma unroll
            for (int b = 0; b < 8; ++b)
                vb[b] = *reinterpret_cast<const float4*>(vq + b * KP);
            float4 whv[JJT];
#pragma unroll
            for (int jl = 0; jl < JJT; ++jl) {
                const float* wb = sW + ((w * JJT + jl) * 3) * KP + g4 * 4;
                float4 wz = *reinterpret_cast<const float4*>(wb);
                float4 wr = *reinterpret_cast<const float4*>(wb + KP);
                whv[jl]   = *reinterpret_cast<const float4*>(wb + 2 * KP);
#pragma unroll
                for (int b = 0; b < 8; ++b) {
                    const int a = (b * JJT + jl) * 4;
                    accf[a+0] = fmaf(vb[b].x, wz.x, accf[a+0]);
                    accf[a+0] = fmaf(vb[b].y, wz.y, accf[a+0]);
                    accf[a+0] = fmaf(vb[b].z, wz.z, accf[a+0]);
                    accf[a+0] = fmaf(vb[b].w, wz.w, accf[a+0]);
                    accf[a+1] = fmaf(vb[b].x, wr.x, accf[a+1]);
                    accf[a+1] = fmaf(vb[b].y, wr.y, accf[a+1]);
                    accf[a+1] = fmaf(vb[b].z, wr.z, accf[a+1]);
                    accf[a+1] = fmaf(vb[b].w, wr.w, accf[a+1]);
                }
            }
            if (g4 < HQ) {   // h-range: gate-h goes to recurrent accumulator (a+2)
#pragma unroll
                for (int jl = 0; jl < JJT; ++jl)
#pragma unroll
                    for (int b = 0; b < 8; ++b) {
                        const int a = (b * JJT + jl) * 4;
                        accf[a+2] = fmaf(vb[b].x, whv[jl].x, accf[a+2]);
                        accf[a+2] = fmaf(vb[b].y, whv[jl].y, accf[a+2]);
                        accf[a+2] = fmaf(vb[b].z, whv[jl].z, accf[a+2]);
                        accf[a+2] = fmaf(vb[b].w, whv[jl].w, accf[a+2]);
                    }
            } else {         // x-range: gate-h goes to input accumulator (a+3)
#pragma unroll
                for (int jl = 0; jl < JJT; ++jl)
#pragma unroll
                    for (int b = 0; b < 8; ++b) {
                        const int a = (b * JJT + jl) * 4;
                        accf[a+3] = fmaf(vb[b].x, whv[jl].x, accf[a+3]);
                        accf[a+3] = fmaf(vb[b].y, whv[jl].y, accf[a+3]);
                        accf[a+3] = fmaf(vb[b].z, whv[jl].z, accf[a+3]);
                        accf[a+3] = fmaf(vb[b].w, whv[jl].w, accf[a+3]);
                    }
            }
        }
        __syncwarp();

        // ---- splitting butterfly reduction over 32 lanes
#pragma unroll
        for (int s = 0; s < 5; ++s) {
            const int n = AC >> (s + 1);
            const bool hi = (lane >> s) & 1;
#pragma unroll
            for (int i = 0; i < n; ++i) {
                float send = hi ? accf[i] : accf[i + n];
                float recv = __shfl_xor_sync(0xffffffffu, send, 1 << s);
                float keep = hi ? accf[i + n] : accf[i];
                accf[i] = keep + recv;
            }
        }
        if (AC == 64)
            *reinterpret_cast<float2*>(sstage + w * AC + a0) = make_float2(accf[0], accf[1]);
        else
            sstage[w * AC + a0] = accf[0];
        __syncthreads();

        // ---- epilogue: gates + state update + DSMEM broadcast + seq write
        if (tid < JT * 8) {
            const int b = tid & 7, jj = tid >> 3;
            const int j = j0 + jj;
            if (j < H) {
                const int wsrc = jj / JJT, jl = jj % JJT;
                float4 gv = *reinterpret_cast<const float4*>(
                    sstage + wsrc * AC + (b * JJT + jl) * 4);
                float az  = gv.x + sbz[jj];
                float ar  = gv.y + sbr[jj];
                float arh = gv.z + sbrh[jj];
                float axh = gv.w + sbxh[jj];
                float z = HSIG ? hsig(az) : sigm(az);
                float r = HSIG ? hsig(ar) : sigm(ar);
                float hh = axh + r * arh;
                if (TANHA) hh = tanhf(hh);
                float hprev = vc[b * KP + j];
                float hn = z * hprev + (1.f - z) * hh;
                if (UM) { if (smk[p * 8 + b] == 0.f) hn = hprev; }

                const uint32_t off = (uint32_t)(((nxt * 8 + b) * KP + j) * 4);
#pragma unroll
                for (int r8 = 0; r8 < 8; r8++) st_cluster_f32(rb[r8] + off, hn);

                if (WSEQ) out_seq[((size_t)(b0 + b) * TT + t) * HP + j] = hn;
            }
        }
        cp_wait0();
        cluster_sync_();
        p = nxt;
    }

    if (!WSEQ) {
        if (tid < JT * 8) {
            const int b = tid & 7, jj = tid >> 3;
            const int j = j0 + jj;
            if (j < H) out_seq[(size_t)(b0 + b) * H + j] = sv[(p * 8 + b) * KP + j];
        }
    }
}

// ===================== small kernels =====================
__global__ void mask_kernel(const float* __restrict__ x, float* __restrict__ m) {
    int idx = blockIdx.x * blockDim.x + threadIdx.x;
    if (idx < BB * TT) {
        float4 v = ((const float4*)x)[idx];
        m[idx] = (v.x != 0.f || v.y != 0.f || v.z != 0.f || v.w != 0.f) ? 1.f : 0.f;
    }
}

__global__ void combine34_kernel(const float* __restrict__ W3, const float* __restrict__ U3,
                                 const float* __restrict__ b3, const float* __restrict__ W4,
                                 const float* __restrict__ U4, const float* __restrict__ b4,
                                 float* __restrict__ Uc, float* __restrict__ Wc,
                                 float* __restrict__ bc) {
    const int NU = 60 * 180, NW = 150 * 180, NBc = 2 * 180;
    for (int e = blockIdx.x * blockDim.x + threadIdx.x; e < NU + NW + NBc;
         e += gridDim.x * blockDim.x) {
        if (e < NU) {
            int k = e / 180, col = e % 180;
            int g = col / 60, jj = col % 60;
            float v = 0.f;
            if (jj < 30) { if (k < 30)  v = U3[k * 90 + g * 30 + jj]; }
            else         { if (k >= 30) v = U4[(k - 30) * 90 + g * 30 + (jj - 30)]; }
            Uc[e] = v;
        } else if (e < NU + NW) {
            int e2 = e - NU;
            int i = e2 / 180, col = e2 % 180;
            int g = col / 60, jj = col % 60;
            Wc[e2] = (jj < 30) ? W3[i * 90 + g * 30 + jj] : W4[i * 90 + g * 30 + (jj - 30)];
        } else {
            int e2 = e - NU - NW;
            int rr = e2 / 180, col = e2 % 180;
            int g = col / 60, jj = col % 60;
            bc[e2] = (jj < 30) ? b3[rr * 90 + g * 30 + jj] : b4[rr * 90 + g * 30 + (jj - 30)];
        }
    }
}

__global__ void z_kernel(const float* __restrict__ h34, const float* __restrict__ eps,
                         float* __restrict__ z) {
    int idx = blockIdx.x * blockDim.x + threadIdx.x;
    if (idx < BB * 30) {
        int b = idx / 30, c = idx % 30;
        z[idx] = h34[b * 60 + c] + expf(0.5f * h34[b * 60 + 30 + c]) * eps[idx];
    }
}

// decoder input, padded stride 36 (pads written as zero)
__global__ void decin_kernel(const float* __restrict__ z, const float* __restrict__ tin2,
                             const float* __restrict__ masks, float* __restrict__ dec_in) {
    const size_t N = (size_t)BB * TT * 36;
    for (size_t idx = (size_t)blockIdx.x * blockDim.x + threadIdx.x; idx < N;
         idx += (size_t)gridDim.x * blockDim.x) {
        size_t b = idx / ((size_t)TT * 36);
        size_t rem = idx % ((size_t)TT * 36);
        size_t t = rem / 36;
        int c = (int)(rem % 36);
        float v = 0.f;
        if (c < 30)      v = z[b * 30 + c] * masks[(b * TT + t) * 32 + c];
        else if (c < 32) v = tin2[(b * TT + t) * 2 + (c - 30)] * masks[(b * TT + t) * 32 + c];
        dec_in[idx] = v;
    }
}

__global__ void dense_kernel(const float* __restrict__ h6, const float* __restrict__ Wd,
                             const float* __restrict__ bd, const float* __restrict__ dec_masks,
                             float* __restrict__ out) {
    int gtid = blockIdx.x * blockDim.x + threadIdx.x;
    int row = gtid >> 5;
    int lane = gtid & 31;
    if (row >= BB * TT) return;
    float s = 0.f;
    const float* hrow = h6 + (size_t)row * 180;   // padded stride
    for (int k = lane; k < 175; k += 32) s = fmaf(hrow[k], Wd[k], s);
#pragma unroll
    for (int off = 16; off; off >>= 1) s += __shfl_down_sync(0xffffffffu, s, off);
    if (lane == 0) out[row] = tanhf(s + bd[0]) * dec_masks[row];
}

// ===================== host-side launch helper =====================
template <int H, int I, int JJT, int NTH, bool HSIG, bool TANHA, bool UM, bool WSEQ>
static void launch_gru(const float* in_seq, const float* U, const float* W, const float* bias,
                       const float* mask, float* out_seq) {
    constexpr int HP = padDim(H), IP = padDim(I), KP = HP + IP;
    constexpr int JT = (H + 7) / 8;
    constexpr int JG = (JT + JJT - 1) / JJT;
    constexpr int JTp = JG * JJT;
    constexpr int AC = 8 * JJT * 4;
    constexpr int SMTOT = JTp * 3 * KP + 16 * KP + JG * AC + 4 * JTp + 16;
    constexpr int smem_bytes = SMTOT * 4;
    cudaFuncSetAttribute(gru_kernel<H, I, JJT, NTH, HSIG, TANHA, UM, WSEQ>,
                         cudaFuncAttributeMaxDynamicSharedMemorySize, smem_bytes);
    gru_kernel<H, I, JJT, NTH, HSIG, TANHA, UM, WSEQ>
        <<<128, NTH, smem_bytes>>>(in_seq, U, W, bias, mask, out_seq);
}

extern "C" void kernel_launch(void* const* d_in, const int* in_sizes, int n_in,
                              void* d_out, int out_size) {
    const float* x         = (const float*)d_in[0];
    const float* tin2      = (const float*)d_in[1];
    const float* masks     = (const float*)d_in[2];
    const float* dec_masks = (const float*)d_in[3];
    const float* eps       = (const float*)d_in[4];
    const float* W1 = (const float*)d_in[5];
    const float* U1 = (const float*)d_in[6];
    const float* b1 = (const float*)d_in[7];
    const float* W2 = (const float*)d_in[8];
    const float* U2 = (const float*)d_in[9];
    const float* b2 = (const float*)d_in[10];
    const float* W3 = (const float*)d_in[11];
    const float* U3 = (const float*)d_in[12];
    const float* b3 = (const float*)d_in[13];
    const float* W4 = (const float*)d_in[14];
    const float* U4 = (const float*)d_in[15];
    const float* b4 = (const float*)d_in[16];
    const float* W5 = (const float*)d_in[17];
    const float* U5 = (const float*)d_in[18];
    const float* b5 = (const float*)d_in[19];
    const float* W6 = (const float*)d_in[20];
    const float* U6 = (const float*)d_in[21];
    const float* b6 = (const float*)d_in[22];
    const float* Wd = (const float*)d_in[23];
    const float* bd = (const float*)d_in[24];
    float* out = (float*)d_out;

    void *pA, *pB, *pM, *pH34, *pZ, *pUc, *pWc, *pBc;
    cudaGetSymbolAddress(&pA, g_bufA);
    cudaGetSymbolAddress(&pB, g_bufB);
    cudaGetSymbolAddress(&pM, g_mask);
    cudaGetSymbolAddress(&pH34, g_h34);
    cudaGetSymbolAddress(&pZ, g_z);
    cudaGetSymbolAddress(&pUc, g_Uc);
    cudaGetSymbolAddress(&pWc, g_Wc);
    cudaGetSymbolAddress(&pBc, g_bc);
    float* bufA = (float*)pA;
    float* bufB = (float*)pB;
    float* mptr = (float*)pM;
    float* h34  = (float*)pH34;
    float* zbuf = (float*)pZ;
    float* Uc   = (float*)pUc;
    float* Wc   = (float*)pWc;
    float* Bc   = (float*)pBc;

    // prep
    mask_kernel<<<(BB * TT + 255) / 256, 256>>>(x, mptr);
    combine34_kernel<<<64, 256>>>(W3, U3, b3, W4, U4, b4, Uc, Wc, Bc);

    // encoder GRU1 (H=175, I=4): JJT=2, 11 warps
    launch_gru<175, 4, 2, 352, true, true, true, true>(x, U1, W1, b1, mptr, bufA);

    // encoder GRU2 (H=150, I=175): JJT=2, 10 warps  (in stride 180, out stride 156)
    launch_gru<150, 175, 2, 320, true, true, true, true>(bufA, U2, W2, b2, mptr, bufB);

    // fused GRU3+GRU4 (H=60, I=150): JJT=1, 8 warps, final state only
    launch_gru<60, 150, 1, 256, false, false, true, false>(bufB, Uc, Wc, Bc, mptr, h34);

    // reparameterize + decoder input (stride 36)
    z_kernel<<<(BB * 30 + 255) / 256, 256>>>(h34, eps, zbuf);
    decin_kernel<<<2048, 256>>>(zbuf, tin2, masks, bufA);

    // decoder GRU5 (H=150, I=32): JJT=2, 10 warps (in stride 36, out stride 156)
    launch_gru<150, 32, 2, 320, true, true, false, true>(bufA, U5, W5, b5, nullptr, bufB);

    // decoder GRU6 (H=175, I=150): JJT=2, 11 warps (in stride 156, out stride 180)
    launch_gru<175, 150, 2, 352, true, true, false, true>(bufB, U6, W6, b6, nullptr, bufA);

    // dense head + output mask (in stride 180)
    dense_kernel<<<(BB * TT + 7) / 8, 256>>>(bufA, Wd, bd, dec_masks, out);
}

// round 6
// speedup vs baseline: 2.6842x; 2.1187x over previous
#include <cuda_runtime.h>
#include <cstdint>
#include <cstdio>

// ===================== problem constants =====================
#define BB 128
#define TT 2048

// ===================== static device scratch =====================
__device__ float g_bufA[(size_t)BB * TT * 180];
__device__ float g_bufB[(size_t)BB * TT * 180];
__device__ float g_mask[(size_t)BB * TT];
__device__ float g_h34[BB * 60];
__device__ float g_z[BB * 30];
__device__ float g_Uc[60 * 180];
__device__ float g_Wc[150 * 180];
__device__ float g_bc[2 * 180];

// ===================== helpers =====================
__host__ __device__ constexpr int padDim(int v) {
    int h = (v + 3) / 4 * 4;
    if (((h / 4) & 1) == 0) h += 4;
    return h;
}

__device__ __forceinline__ uint32_t smem_u32(const void* p) {
    uint32_t a;
    asm("{ .reg .u64 t; cvta.to.shared.u64 t, %1; cvt.u32.u64 %0, t; }" : "=r"(a) : "l"(p));
    return a;
}
__device__ __forceinline__ uint32_t mapa_shared(uint32_t local, uint32_t rank) {
    uint32_t r;
    asm("mapa.shared::cluster.u32 %0, %1, %2;" : "=r"(r) : "r"(local), "r"(rank));
    return r;
}
__device__ __forceinline__ void st_cluster_f32(uint32_t addr, float v) {
    asm volatile("st.shared::cluster.b32 [%0], %1;" :: "r"(addr), "r"(__float_as_uint(v)));
}
__device__ __forceinline__ void cluster_sync_() {
    asm volatile("barrier.cluster.arrive.aligned;" ::: "memory");
    asm volatile("barrier.cluster.wait.aligned;" ::: "memory");
}
__device__ __forceinline__ void cp_async16(uint32_t dst, const void* src) {
    asm volatile("cp.async.cg.shared.global [%0], [%1], 16;" :: "r"(dst), "l"(src));
}
__device__ __forceinline__ void cp_async4(uint32_t dst, const void* src) {
    asm volatile("cp.async.ca.shared.global [%0], [%1], 4;" :: "r"(dst), "l"(src));
}
__device__ __forceinline__ void cp_commit() {
    asm volatile("cp.async.commit_group;" ::: "memory");
}
__device__ __forceinline__ void cp_wait0() {
    asm volatile("cp.async.wait_group 0;" ::: "memory");
}

__device__ __forceinline__ float hsig(float v) { return fminf(fmaxf(0.2f * v + 0.5f, 0.f), 1.f); }
__device__ __forceinline__ float sigm(float v) { return 1.f / (1.f + expf(-v)); }

// ===================== persistent GRU kernel (register-tiled, 2 CTA/SM) =====================
// 32 clusters of 8 CTAs; cluster handles BT=4 batch rows; CTA rank owns hidden
// tile [j0, j0+JT). One warp owns (4 b) x (4 jj); lanes split K-quads 32 ways.
// Butterfly reduction leaves all 4 gate accumulators in the owner lane -> full
// in-register epilogue (gates, state update, DSMEM broadcast, seq store).
// One cluster barrier per step. 2 CTAs/SM so sync latency of one cluster
// overlaps compute of the other.
template <int H, int I, int NTH, bool HSIG, bool TANHA, bool UM, bool WSEQ>
__global__ void __cluster_dims__(8, 1, 1) __launch_bounds__(NTH, 2)
gru_kernel(const float* __restrict__ in_seq, const float* __restrict__ U,
           const float* __restrict__ W, const float* __restrict__ bias,
           const float* __restrict__ mask, float* __restrict__ out_seq)
{
    constexpr int BT = 4, JJT = 4;
    constexpr int HP = padDim(H), IP = padDim(I), KP = HP + IP;
    constexpr int Q = KP / 4, HQ = HP / 4;
    constexpr int JT = (H + 7) / 8;
    constexpr int JG = (JT + JJT - 1) / JJT;
    constexpr int JTp = JG * JJT;
    constexpr int H3 = 3 * H;
    static_assert(NTH == 32 * JG, "threads = 32 per jj-group");

    extern __shared__ float smem[];
    float* sW   = smem;                     // JTp*3*KP (rows zero-padded)
    float* sv   = sW + JTp * 3 * KP;        // 2*BT*KP  (double-buffered [h|x])
    float* sbz  = sv + 2 * BT * KP;         // JTp
    float* sbr  = sbz + JTp;
    float* sbrh = sbr + JTp;
    float* sbxh = sbrh + JTp;
    float* smk  = sbxh + JTp;               // 2*BT
    constexpr int SMTOT = JTp * 3 * KP + 2 * BT * KP + 4 * JTp + 2 * BT;

    const int tid  = threadIdx.x;
    const int rank = blockIdx.x & 7;
    const int ci   = blockIdx.x >> 3;
    const int b0   = ci * BT;
    const int j0   = rank * JT;

    for (int e = tid; e < SMTOT; e += NTH) smem[e] = 0.f;
    __syncthreads();

    // weights: row (jj,g) = [U[:,g*H+j] (k<H) | W[:,g*H+j] (i<I)], zero-padded
    for (int e = tid; e < JT * 3 * KP; e += NTH) {
        int jj = e / (3 * KP);
        int r  = e - jj * (3 * KP);
        int g  = r / KP;
        int k  = r - g * KP;
        int j  = j0 + jj;
        float val = 0.f;
        if (j < H) {
            if (k < HP) { if (k < H) val = U[k * H3 + g * H + j]; }
            else { int i = k - HP; if (i < I) val = W[i * H3 + g * H + j]; }
        }
        sW[(jj * 3 + g) * KP + k] = val;
    }
    if (tid < JT) {
        int j = j0 + tid;
        if (j < H) {
            sbz[tid]  = bias[j] + bias[H3 + j];
            sbr[tid]  = bias[H + j] + bias[H3 + H + j];
            sbxh[tid] = bias[2 * H + j];
            sbrh[tid] = bias[H3 + 2 * H + j];
        }
    }
    __syncthreads();

    const uint32_t svu = smem_u32(sv);
    uint32_t rb[8];
#pragma unroll
    for (int r = 0; r < 8; r++) rb[r] = mapa_shared(svu, (uint32_t)r);

    // stage x(0), mask(0) into phase 0
    constexpr int XOPS = BT * (IP / 4);
    for (int e = tid; e < XOPS; e += NTH) {
        int bb = e / (IP / 4), i4 = e - bb * (IP / 4);
        cp_async16(svu + (uint32_t)((bb * KP + HP + i4 * 4) * 4),
                   in_seq + ((size_t)(b0 + bb) * TT) * IP + i4 * 4);
    }
    if (UM && tid < BT)
        cp_async4(smem_u32(smk + tid), mask + (size_t)(b0 + tid) * TT);
    cp_commit();
    cp_wait0();
    cluster_sync_();

    const int w = tid >> 5, lane = tid & 31;

    int p = 0;
    for (int t = 0; t < TT; t++) {
        const int nxt = 1 - p;
        // prefetch x(t+1), mask(t+1)
        if (t + 1 < TT) {
            for (int e = tid; e < XOPS; e += NTH) {
                int bb = e / (IP / 4), i4 = e - bb * (IP / 4);
                cp_async16(svu + (uint32_t)(((nxt * BT + bb) * KP + HP + i4 * 4) * 4),
                           in_seq + ((size_t)(b0 + bb) * TT + (t + 1)) * IP + i4 * 4);
            }
            if (UM && tid < BT)
                cp_async4(smem_u32(smk + nxt * BT + tid),
                          mask + (size_t)(b0 + tid) * TT + (t + 1));
        }
        cp_commit();

        // ---- main accumulation: warp covers 4 b x 4 jj, lanes stride quads
        const float* vc = sv + p * BT * KP;
        float accf[64];
#pragma unroll
        for (int a = 0; a < 64; a++) accf[a] = 0.f;

        for (int g4 = lane; g4 < Q; g4 += 32) {
            const float* vq = vc + g4 * 4;
            float4 vb[BT];
#pragma unroll
            for (int b = 0; b < BT; ++b)
                vb[b] = *reinterpret_cast<const float4*>(vq + b * KP);
            float4 whv[JJT];
#pragma unroll
            for (int jl = 0; jl < JJT; ++jl) {
                const float* wb = sW + ((w * JJT + jl) * 3) * KP + g4 * 4;
                float4 wz = *reinterpret_cast<const float4*>(wb);
                float4 wr = *reinterpret_cast<const float4*>(wb + KP);
                whv[jl]   = *reinterpret_cast<const float4*>(wb + 2 * KP);
#pragma unroll
                for (int b = 0; b < BT; ++b) {
                    const int a = (b * JJT + jl) * 4;
                    accf[a+0] = fmaf(vb[b].x, wz.x, accf[a+0]);
                    accf[a+0] = fmaf(vb[b].y, wz.y, accf[a+0]);
                    accf[a+0] = fmaf(vb[b].z, wz.z, accf[a+0]);
                    accf[a+0] = fmaf(vb[b].w, wz.w, accf[a+0]);
                    accf[a+1] = fmaf(vb[b].x, wr.x, accf[a+1]);
                    accf[a+1] = fmaf(vb[b].y, wr.y, accf[a+1]);
                    accf[a+1] = fmaf(vb[b].z, wr.z, accf[a+1]);
                    accf[a+1] = fmaf(vb[b].w, wr.w, accf[a+1]);
                }
            }
            if (g4 < HQ) {   // h-range: gate-h -> recurrent accumulator (a+2)
#pragma unroll
                for (int jl = 0; jl < JJT; ++jl)
#pragma unroll
                    for (int b = 0; b < BT; ++b) {
                        const int a = (b * JJT + jl) * 4;
                        accf[a+2] = fmaf(vb[b].x, whv[jl].x, accf[a+2]);
                        accf[a+2] = fmaf(vb[b].y, whv[jl].y, accf[a+2]);
                        accf[a+2] = fmaf(vb[b].z, whv[jl].z, accf[a+2]);
                        accf[a+2] = fmaf(vb[b].w, whv[jl].w, accf[a+2]);
                    }
            } else {         // x-range: gate-h -> input accumulator (a+3)
#pragma unroll
                for (int jl = 0; jl < JJT; ++jl)
#pragma unroll
                    for (int b = 0; b < BT; ++b) {
                        const int a = (b * JJT + jl) * 4;
                        accf[a+3] = fmaf(vb[b].x, whv[jl].x, accf[a+3]);
                        accf[a+3] = fmaf(vb[b].y, whv[jl].y, accf[a+3]);
                        accf[a+3] = fmaf(vb[b].z, whv[jl].z, accf[a+3]);
                        accf[a+3] = fmaf(vb[b].w, whv[jl].w, accf[a+3]);
                    }
            }
        }

        // ---- splitting butterfly: 4 rounds over lane bits 0..3
#pragma unroll
        for (int s = 0; s < 4; ++s) {
            const int n = 64 >> (s + 1);
            const bool hi = (lane >> s) & 1;
#pragma unroll
            for (int i = 0; i < n; ++i) {
                float send = hi ? accf[i] : accf[i + n];
                float recv = __shfl_xor_sync(0xffffffffu, send, 1 << s);
                accf[i] = (hi ? accf[i + n] : accf[i]) + recv;
            }
        }
        // finish across lane bit 4, keeping all 4 gate accs (dup in l, l^16)
#pragma unroll
        for (int i = 0; i < 4; ++i)
            accf[i] += __shfl_xor_sync(0xffffffffu, accf[i], 16);

        // ---- in-register epilogue on owner lanes
        if (lane < 16) {
            const int item = ((lane & 1) << 3) | ((lane & 2) << 1) |
                             ((lane & 4) >> 1) | ((lane & 8) >> 3);
            const int b = item >> 2, jl = item & 3;
            const int jj = w * JJT + jl;
            const int j  = j0 + jj;
            if (jj < JT && j < H) {
                float az  = accf[0] + sbz[jj];
                float ar  = accf[1] + sbr[jj];
                float arh = accf[2] + sbrh[jj];
                float axh = accf[3] + sbxh[jj];
                float z = HSIG ? hsig(az) : sigm(az);
                float r = HSIG ? hsig(ar) : sigm(ar);
                float hh = axh + r * arh;
                if (TANHA) hh = tanhf(hh);
                float hprev = vc[b * KP + j];
                float hn = z * hprev + (1.f - z) * hh;
                if (UM) { if (smk[p * BT + b] == 0.f) hn = hprev; }

                const uint32_t off = (uint32_t)(((nxt * BT + b) * KP + j) * 4);
#pragma unroll
                for (int r8 = 0; r8 < 8; r8++) st_cluster_f32(rb[r8] + off, hn);

                if (WSEQ) out_seq[((size_t)(b0 + b) * TT + t) * HP + j] = hn;
            }
        }
        cp_wait0();
        cluster_sync_();
        p = nxt;
    }

    if (!WSEQ) {
        if (tid < JT * BT) {
            const int b = tid & 3, jj = tid >> 2;
            const int j = j0 + jj;
            if (j < H) out_seq[(size_t)(b0 + b) * H + j] = sv[(p * BT + b) * KP + j];
        }
    }
}

// ===================== small kernels =====================
__global__ void mask_kernel(const float* __restrict__ x, float* __restrict__ m) {
    int idx = blockIdx.x * blockDim.x + threadIdx.x;
    if (idx < BB * TT) {
        float4 v = ((const float4*)x)[idx];
        m[idx] = (v.x != 0.f || v.y != 0.f || v.z != 0.f || v.w != 0.f) ? 1.f : 0.f;
    }
}

__global__ void combine34_kernel(const float* __restrict__ W3, const float* __restrict__ U3,
                                 const float* __restrict__ b3, const float* __restrict__ W4,
                                 const float* __restrict__ U4, const float* __restrict__ b4,
                                 float* __restrict__ Uc, float* __restrict__ Wc,
                                 float* __restrict__ bc) {
    const int NU = 60 * 180, NW = 150 * 180, NBc = 2 * 180;
    for (int e = blockIdx.x * blockDim.x + threadIdx.x; e < NU + NW + NBc;
         e += gridDim.x * blockDim.x) {
        if (e < NU) {
            int k = e / 180, col = e % 180;
            int g = col / 60, jj = col % 60;
            float v = 0.f;
            if (jj < 30) { if (k < 30)  v = U3[k * 90 + g * 30 + jj]; }
            else         { if (k >= 30) v = U4[(k - 30) * 90 + g * 30 + (jj - 30)]; }
            Uc[e] = v;
        } else if (e < NU + NW) {
            int e2 = e - NU;
            int i = e2 / 180, col = e2 % 180;
            int g = col / 60, jj = col % 60;
            Wc[e2] = (jj < 30) ? W3[i * 90 + g * 30 + jj] : W4[i * 90 + g * 30 + (jj - 30)];
        } else {
            int e2 = e - NU - NW;
            int rr = e2 / 180, col = e2 % 180;
            int g = col / 60, jj = col % 60;
            bc[e2] = (jj < 30) ? b3[rr * 90 + g * 30 + jj] : b4[rr * 90 + g * 30 + (jj - 30)];
        }
    }
}

__global__ void z_kernel(const float* __restrict__ h34, const float* __restrict__ eps,
                         float* __restrict__ z) {
    int idx = blockIdx.x * blockDim.x + threadIdx.x;
    if (idx < BB * 30) {
        int b = idx / 30, c = idx % 30;
        z[idx] = h34[b * 60 + c] + expf(0.5f * h34[b * 60 + 30 + c]) * eps[idx];
    }
}

// decoder input, padded stride 36 (pads written as zero)
__global__ void decin_kernel(const float* __restrict__ z, const float* __restrict__ tin2,
                             const float* __restrict__ masks, float* __restrict__ dec_in) {
    const size_t N = (size_t)BB * TT * 36;
    for (size_t idx = (size_t)blockIdx.x * blockDim.x + threadIdx.x; idx < N;
         idx += (size_t)gridDim.x * blockDim.x) {
        size_t b = idx / ((size_t)TT * 36);
        size_t rem = idx % ((size_t)TT * 36);
        size_t t = rem / 36;
        int c = (int)(rem % 36);
        float v = 0.f;
        if (c < 30)      v = z[b * 30 + c] * masks[(b * TT + t) * 32 + c];
        else if (c < 32) v = tin2[(b * TT + t) * 2 + (c - 30)] * masks[(b * TT + t) * 32 + c];
        dec_in[idx] = v;
    }
}

__global__ void dense_kernel(const float* __restrict__ h6, const float* __restrict__ Wd,
                             const float* __restrict__ bd, const float* __restrict__ dec_masks,
                             float* __restrict__ out) {
    int gtid = blockIdx.x * blockDim.x + threadIdx.x;
    int row = gtid >> 5;
    int lane = gtid & 31;
    if (row >= BB * TT) return;
    float s = 0.f;
    const float* hrow = h6 + (size_t)row * 180;   // padded stride
    for (int k = lane; k < 175; k += 32) s = fmaf(hrow[k], Wd[k], s);
#pragma unroll
    for (int off = 16; off; off >>= 1) s += __shfl_down_sync(0xffffffffu, s, off);
    if (lane == 0) out[row] = tanhf(s + bd[0]) * dec_masks[row];
}

// ===================== host-side launch helper =====================
template <int H, int I, int NTH, bool HSIG, bool TANHA, bool UM, bool WSEQ>
static void launch_gru(const float* in_seq, const float* U, const float* W, const float* bias,
                       const float* mask, float* out_seq) {
    constexpr int BT = 4, JJT = 4;
    constexpr int HP = padDim(H), IP = padDim(I), KP = HP + IP;
    constexpr int JT = (H + 7) / 8;
    constexpr int JG = (JT + JJT - 1) / JJT;
    constexpr int JTp = JG * JJT;
    constexpr int SMTOT = JTp * 3 * KP + 2 * BT * KP + 4 * JTp + 2 * BT;
    constexpr int smem_bytes = SMTOT * 4;
    auto fn = gru_kernel<H, I, NTH, HSIG, TANHA, UM, WSEQ>;
    cudaFuncSetAttribute(fn, cudaFuncAttributeMaxDynamicSharedMemorySize, smem_bytes);
    cudaFuncSetAttribute(fn, cudaFuncAttributeNonPortableClusterSizeAllowed, 1);
    fn<<<256, NTH, smem_bytes>>>(in_seq, U, W, bias, mask, out_seq);
}

extern "C" void kernel_launch(void* const* d_in, const int* in_sizes, int n_in,
                              void* d_out, int out_size) {
    const float* x         = (const float*)d_in[0];
    const float* tin2      = (const float*)d_in[1];
    const float* masks     = (const float*)d_in[2];
    const float* dec_masks = (const float*)d_in[3];
    const float* eps       = (const float*)d_in[4];
    const float* W1 = (const float*)d_in[5];
    const float* U1 = (const float*)d_in[6];
    const float* b1 = (const float*)d_in[7];
    const float* W2 = (const float*)d_in[8];
    const float* U2 = (const float*)d_in[9];
    const float* b2 = (const float*)d_in[10];
    const float* W3 = (const float*)d_in[11];
    const float* U3 = (const float*)d_in[12];
    const float* b3 = (const float*)d_in[13];
    const float* W4 = (const float*)d_in[14];
    const float* U4 = (const float*)d_in[15];
    const float* b4 = (const float*)d_in[16];
    const float* W5 = (const float*)d_in[17];
    const float* U5 = (const float*)d_in[18];
    const float* b5 = (const float*)d_in[19];
    const float* W6 = (const float*)d_in[20];
    const float* U6 = (const float*)d_in[21];
    const float* b6 = (const float*)d_in[22];
    const float* Wd = (const float*)d_in[23];
    const float* bd = (const float*)d_in[24];
    float* out = (float*)d_out;

    void *pA, *pB, *pM, *pH34, *pZ, *pUc, *pWc, *pBc;
    cudaGetSymbolAddress(&pA, g_bufA);
    cudaGetSymbolAddress(&pB, g_bufB);
    cudaGetSymbolAddress(&pM, g_mask);
    cudaGetSymbolAddress(&pH34, g_h34);
    cudaGetSymbolAddress(&pZ, g_z);
    cudaGetSymbolAddress(&pUc, g_Uc);
    cudaGetSymbolAddress(&pWc, g_Wc);
    cudaGetSymbolAddress(&pBc, g_bc);
    float* bufA = (float*)pA;
    float* bufB = (float*)pB;
    float* mptr = (float*)pM;
    float* h34  = (float*)pH34;
    float* zbuf = (float*)pZ;
    float* Uc   = (float*)pUc;
    float* Wc   = (float*)pWc;
    float* Bc   = (float*)pBc;

    // prep
    mask_kernel<<<(BB * TT + 255) / 256, 256>>>(x, mptr);
    combine34_kernel<<<64, 256>>>(W3, U3, b3, W4, U4, b4, Uc, Wc, Bc);

    // encoder GRU1 (H=175, I=4): JT=22, JG=6 -> 192 threads
    launch_gru<175, 4, 192, true, true, true, true>(x, U1, W1, b1, mptr, bufA);

    // encoder GRU2 (H=150, I=175): JT=19, JG=5 -> 160 threads
    launch_gru<150, 175, 160, true, true, true, true>(bufA, U2, W2, b2, mptr, bufB);

    // fused GRU3+GRU4 (H=60, I=150): JT=8, JG=2 -> 64 threads, final state only
    launch_gru<60, 150, 64, false, false, true, false>(bufB, Uc, Wc, Bc, mptr, h34);

    // reparameterize + decoder input (stride 36)
    z_kernel<<<(BB * 30 + 255) / 256, 256>>>(h34, eps, zbuf);
    decin_kernel<<<2048, 256>>>(zbuf, tin2, masks, bufA);

    // decoder GRU5 (H=150, I=32): 160 threads
    launch_gru<150, 32, 160, true, true, false, true>(bufA, U5, W5, b5, nullptr, bufB);

    // decoder GRU6 (H=175, I=150): 192 threads
    launch_gru<175, 150, 192, true, true, false, true>(bufB, U6, W6, b6, nullptr, bufA);

    // dense head + output mask (stride 180)
    dense_kernel<<<(BB * TT + 7) / 8, 256>>>(bufA, Wd, bd, dec_masks, out);
}

// round 7
// speedup vs baseline: 2.6871x; 1.0011x over previous
#include <cuda_runtime.h>
#include <cstdint>
#include <cstdio>

// ===================== problem constants =====================
#define BB 128
#define TT 2048

// ===================== static device scratch =====================
__device__ float g_bufA[(size_t)BB * TT * 180];
__device__ float g_bufB[(size_t)BB * TT * 180];
__device__ float g_mask[(size_t)BB * TT];
__device__ float g_h34[BB * 60];
__device__ float g_z[BB * 30];
__device__ float g_Uc[60 * 180];
__device__ float g_Wc[150 * 180];
__device__ float g_bc[2 * 180];

// ===================== helpers =====================
__host__ __device__ constexpr int padDim(int v) {
    int h = (v + 3) / 4 * 4;
    if (((h / 4) & 1) == 0) h += 4;
    return h;
}

__device__ __forceinline__ uint32_t smem_u32(const void* p) {
    uint32_t a;
    asm("{ .reg .u64 t; cvta.to.shared.u64 t, %1; cvt.u32.u64 %0, t; }" : "=r"(a) : "l"(p));
    return a;
}
__device__ __forceinline__ uint32_t mapa_shared(uint32_t local, uint32_t rank) {
    uint32_t r;
    asm("mapa.shared::cluster.u32 %0, %1, %2;" : "=r"(r) : "r"(local), "r"(rank));
    return r;
}
__device__ __forceinline__ void st_cluster_f32(uint32_t addr, float v) {
    asm volatile("st.shared::cluster.b32 [%0], %1;" :: "r"(addr), "r"(__float_as_uint(v)));
}
__device__ __forceinline__ void cluster_sync_() {
    asm volatile("barrier.cluster.arrive.aligned;" ::: "memory");
    asm volatile("barrier.cluster.wait.aligned;" ::: "memory");
}
__device__ __forceinline__ void cp_async16(uint32_t dst, const void* src) {
    asm volatile("cp.async.cg.shared.global [%0], [%1], 16;" :: "r"(dst), "l"(src));
}
__device__ __forceinline__ void cp_async4(uint32_t dst, const void* src) {
    asm volatile("cp.async.ca.shared.global [%0], [%1], 4;" :: "r"(dst), "l"(src));
}
__device__ __forceinline__ void cp_commit() {
    asm volatile("cp.async.commit_group;" ::: "memory");
}
__device__ __forceinline__ void cp_wait0() {
    asm volatile("cp.async.wait_group 0;" ::: "memory");
}

__device__ __forceinline__ float hsig(float v) { return fminf(fmaxf(0.2f * v + 0.5f, 0.f), 1.f); }
__device__ __forceinline__ float sigm(float v) { return 1.f / (1.f + expf(-v)); }

// ===================== persistent GRU kernel (register-tiled, 2 CTA/SM) =====================
// 32 clusters of 8 CTAs; cluster handles BT=4 batch rows; CTA rank owns hidden
// tile [j0, j0+JT). One warp owns (4 b) x (4 jj); lanes split K-quads 32 ways.
// Butterfly reduction leaves all 4 gate accumulators in the owner lane -> full
// in-register epilogue (gates, state update, DSMEM broadcast, seq store).
// One cluster barrier per step. 2 CTAs/SM so sync latency of one cluster
// overlaps compute of the other.
template <int H, int I, int NTH, bool HSIG, bool TANHA, bool UM, bool WSEQ>
__global__ void __cluster_dims__(8, 1, 1) __launch_bounds__(NTH, 2)
gru_kernel(const float* __restrict__ in_seq, const float* __restrict__ U,
           const float* __restrict__ W, const float* __restrict__ bias,
           const float* __restrict__ mask, float* __restrict__ out_seq)
{
    constexpr int BT = 4, JJT = 4;
    constexpr int HP = padDim(H), IP = padDim(I), KP = HP + IP;
    constexpr int Q = KP / 4, HQ = HP / 4;
    constexpr int JT = (H + 7) / 8;
    constexpr int JG = (JT + JJT - 1) / JJT;
    constexpr int JTp = JG * JJT;
    constexpr int H3 = 3 * H;
    static_assert(NTH == 32 * JG, "threads = 32 per jj-group");

    extern __shared__ float smem[];
    float* sW   = smem;                     // JTp*3*KP (rows zero-padded)
    float* sv   = sW + JTp * 3 * KP;        // 2*BT*KP  (double-buffered [h|x])
    float* sbz  = sv + 2 * BT * KP;         // JTp
    float* sbr  = sbz + JTp;
    float* sbrh = sbr + JTp;
    float* sbxh = sbrh + JTp;
    float* smk  = sbxh + JTp;               // 2*BT
    constexpr int SMTOT = JTp * 3 * KP + 2 * BT * KP + 4 * JTp + 2 * BT;

    const int tid  = threadIdx.x;
    const int rank = blockIdx.x & 7;
    const int ci   = blockIdx.x >> 3;
    const int b0   = ci * BT;
    const int j0   = rank * JT;

    for (int e = tid; e < SMTOT; e += NTH) smem[e] = 0.f;
    __syncthreads();

    // weights: row (jj,g) = [U[:,g*H+j] (k<H) | W[:,g*H+j] (i<I)], zero-padded
    for (int e = tid; e < JT * 3 * KP; e += NTH) {
        int jj = e / (3 * KP);
        int r  = e - jj * (3 * KP);
        int g  = r / KP;
        int k  = r - g * KP;
        int j  = j0 + jj;
        float val = 0.f;
        if (j < H) {
            if (k < HP) { if (k < H) val = U[k * H3 + g * H + j]; }
            else { int i = k - HP; if (i < I) val = W[i * H3 + g * H + j]; }
        }
        sW[(jj * 3 + g) * KP + k] = val;
    }
    if (tid < JT) {
        int j = j0 + tid;
        if (j < H) {
            sbz[tid]  = bias[j] + bias[H3 + j];
            sbr[tid]  = bias[H + j] + bias[H3 + H + j];
            sbxh[tid] = bias[2 * H + j];
            sbrh[tid] = bias[H3 + 2 * H + j];
        }
    }
    __syncthreads();

    const uint32_t svu = smem_u32(sv);
    uint32_t rb[8];
#pragma unroll
    for (int r = 0; r < 8; r++) rb[r] = mapa_shared(svu, (uint32_t)r);

    // stage x(0), mask(0) into phase 0
    constexpr int XOPS = BT * (IP / 4);
    for (int e = tid; e < XOPS; e += NTH) {
        int bb = e / (IP / 4), i4 = e - bb * (IP / 4);
        cp_async16(svu + (uint32_t)((bb * KP + HP + i4 * 4) * 4),
                   in_seq + ((size_t)(b0 + bb) * TT) * IP + i4 * 4);
    }
    if (UM && tid < BT)
        cp_async4(smem_u32(smk + tid), mask + (size_t)(b0 + tid) * TT);
    cp_commit();
    cp_wait0();
    cluster_sync_();

    const int w = tid >> 5, lane = tid & 31;

    int p = 0;
    for (int t = 0; t < TT; t++) {
        const int nxt = 1 - p;
        // prefetch x(t+1), mask(t+1)
        if (t + 1 < TT) {
            for (int e = tid; e < XOPS; e += NTH) {
                int bb = e / (IP / 4), i4 = e - bb * (IP / 4);
                cp_async16(svu + (uint32_t)(((nxt * BT + bb) * KP + HP + i4 * 4) * 4),
                           in_seq + ((size_t)(b0 + bb) * TT + (t + 1)) * IP + i4 * 4);
            }
            if (UM && tid < BT)
                cp_async4(smem_u32(smk + nxt * BT + tid),
                          mask + (size_t)(b0 + tid) * TT + (t + 1));
        }
        cp_commit();

        // ---- main accumulation: warp covers 4 b x 4 jj, lanes stride quads
        const float* vc = sv + p * BT * KP;
        float accf[64];
#pragma unroll
        for (int a = 0; a < 64; a++) accf[a] = 0.f;

        for (int g4 = lane; g4 < Q; g4 += 32) {
            const float* vq = vc + g4 * 4;
            float4 vb[BT];
#pragma unroll
            for (int b = 0; b < BT; ++b)
                vb[b] = *reinterpret_cast<const float4*>(vq + b * KP);
            float4 whv[JJT];
#pragma unroll
            for (int jl = 0; jl < JJT; ++jl) {
                const float* wb = sW + ((w * JJT + jl) * 3) * KP + g4 * 4;
                float4 wz = *reinterpret_cast<const float4*>(wb);
                float4 wr = *reinterpret_cast<const float4*>(wb + KP);
                whv[jl]   = *reinterpret_cast<const float4*>(wb + 2 * KP);
#pragma unroll
                for (int b = 0; b < BT; ++b) {
                    const int a = (b * JJT + jl) * 4;
                    accf[a+0] = fmaf(vb[b].x, wz.x, accf[a+0]);
                    accf[a+0] = fmaf(vb[b].y, wz.y, accf[a+0]);
                    accf[a+0] = fmaf(vb[b].z, wz.z, accf[a+0]);
                    accf[a+0] = fmaf(vb[b].w, wz.w, accf[a+0]);
                    accf[a+1] = fmaf(vb[b].x, wr.x, accf[a+1]);
                    accf[a+1] = fmaf(vb[b].y, wr.y, accf[a+1]);
                    accf[a+1] = fmaf(vb[b].z, wr.z, accf[a+1]);
                    accf[a+1] = fmaf(vb[b].w, wr.w, accf[a+1]);
                }
            }
            if (g4 < HQ) {   // h-range: gate-h -> recurrent accumulator (a+2)
#pragma unroll
                for (int jl = 0; jl < JJT; ++jl)
#pragma unroll
                    for (int b = 0; b < BT; ++b) {
                        const int a = (b * JJT + jl) * 4;
                        accf[a+2] = fmaf(vb[b].x, whv[jl].x, accf[a+2]);
                        accf[a+2] = fmaf(vb[b].y, whv[jl].y, accf[a+2]);
                        accf[a+2] = fmaf(vb[b].z, whv[jl].z, accf[a+2]);
                        accf[a+2] = fmaf(vb[b].w, whv[jl].w, accf[a+2]);
                    }
            } else {         // x-range: gate-h -> input accumulator (a+3)
#pragma unroll
                for (int jl = 0; jl < JJT; ++jl)
#pragma unroll
                    for (int b = 0; b < BT; ++b) {
                        const int a = (b * JJT + jl) * 4;
                        accf[a+3] = fmaf(vb[b].x, whv[jl].x, accf[a+3]);
                        accf[a+3] = fmaf(vb[b].y, whv[jl].y, accf[a+3]);
                        accf[a+3] = fmaf(vb[b].z, whv[jl].z, accf[a+3]);
                        accf[a+3] = fmaf(vb[b].w, whv[jl].w, accf[a+3]);
                    }
            }
        }

        // ---- splitting butterfly: 4 rounds over lane bits 0..3
#pragma unroll
        for (int s = 0; s < 4; ++s) {
            const int n = 64 >> (s + 1);
            const bool hi = (lane >> s) & 1;
#pragma unroll
            for (int i = 0; i < n; ++i) {
                float send = hi ? accf[i] : accf[i + n];
                float recv = __shfl_xor_sync(0xffffffffu, send, 1 << s);
                accf[i] = (hi ? accf[i + n] : accf[i]) + recv;
            }
        }
        // finish across lane bit 4, keeping all 4 gate accs (dup in l, l^16)
#pragma unroll
        for (int i = 0; i < 4; ++i)
            accf[i] += __shfl_xor_sync(0xffffffffu, accf[i], 16);

        // ---- in-register epilogue on owner lanes
        if (lane < 16) {
            const int item = ((lane & 1) << 3) | ((lane & 2) << 1) |
                             ((lane & 4) >> 1) | ((lane & 8) >> 3);
            const int b = item >> 2, jl = item & 3;
            const int jj = w * JJT + jl;
            const int j  = j0 + jj;
            if (jj < JT && j < H) {
                float az  = accf[0] + sbz[jj];
                float ar  = accf[1] + sbr[jj];
                float arh = accf[2] + sbrh[jj];
                float axh = accf[3] + sbxh[jj];
                float z = HSIG ? hsig(az) : sigm(az);
                float r = HSIG ? hsig(ar) : sigm(ar);
                float hh = axh + r * arh;
                if (TANHA) hh = tanhf(hh);
                float hprev = vc[b * KP + j];
                float hn = z * hprev + (1.f - z) * hh;
                if (UM) { if (smk[p * BT + b] == 0.f) hn = hprev; }

                const uint32_t off = (uint32_t)(((nxt * BT + b) * KP + j) * 4);
#pragma unroll
                for (int r8 = 0; r8 < 8; r8++) st_cluster_f32(rb[r8] + off, hn);

                if (WSEQ) out_seq[((size_t)(b0 + b) * TT + t) * HP + j] = hn;
            }
        }
        cp_wait0();
        cluster_sync_();
        p = nxt;
    }

    if (!WSEQ) {
        if (tid < JT * BT) {
            const int b = tid & 3, jj = tid >> 2;
            const int j = j0 + jj;
            if (j < H) out_seq[(size_t)(b0 + b) * H + j] = sv[(p * BT + b) * KP + j];
        }
    }
}

// ===================== small kernels =====================
__global__ void mask_kernel(const float* __restrict__ x, float* __restrict__ m) {
    int idx = blockIdx.x * blockDim.x + threadIdx.x;
    if (idx < BB * TT) {
        float4 v = ((const float4*)x)[idx];
        m[idx] = (v.x != 0.f || v.y != 0.f || v.z != 0.f || v.w != 0.f) ? 1.f : 0.f;
    }
}

__global__ void combine34_kernel(const float* __restrict__ W3, const float* __restrict__ U3,
                                 const float* __restrict__ b3, const float* __restrict__ W4,
                                 const float* __restrict__ U4, const float* __restrict__ b4,
                                 float* __restrict__ Uc, float* __restrict__ Wc,
                                 float* __restrict__ bc) {
    const int NU = 60 * 180, NW = 150 * 180, NBc = 2 * 180;
    for (int e = blockIdx.x * blockDim.x + threadIdx.x; e < NU + NW + NBc;
         e += gridDim.x * blockDim.x) {
        if (e < NU) {
            int k = e / 180, col = e % 180;
            int g = col / 60, jj = col % 60;
            float v = 0.f;
            if (jj < 30) { if (k < 30)  v = U3[k * 90 + g * 30 + jj]; }
            else         { if (k >= 30) v = U4[(k - 30) * 90 + g * 30 + (jj - 30)]; }
            Uc[e] = v;
        } else if (e < NU + NW) {
            int e2 = e - NU;
            int i = e2 / 180, col = e2 % 180;
            int g = col / 60, jj = col % 60;
            Wc[e2] = (jj < 30) ? W3[i * 90 + g * 30 + jj] : W4[i * 90 + g * 30 + (jj - 30)];
        } else {
            int e2 = e - NU - NW;
            int rr = e2 / 180, col = e2 % 180;
            int g = col / 60, jj = col % 60;
            bc[e2] = (jj < 30) ? b3[rr * 90 + g * 30 + jj] : b4[rr * 90 + g * 30 + (jj - 30)];
        }
    }
}

__global__ void z_kernel(const float* __restrict__ h34, const float* __restrict__ eps,
                         float* __restrict__ z) {
    int idx = blockIdx.x * blockDim.x + threadIdx.x;
    if (idx < BB * 30) {
        int b = idx / 30, c = idx % 30;
        z[idx] = h34[b * 60 + c] + expf(0.5f * h34[b * 60 + 30 + c]) * eps[idx];
    }
}

// decoder input, padded stride 36 (pads written as zero)
__global__ void decin_kernel(const float* __restrict__ z, const float* __restrict__ tin2,
                             const float* __restrict__ masks, float* __restrict__ dec_in) {
    const size_t N = (size_t)BB * TT * 36;
    for (size_t idx = (size_t)blockIdx.x * blockDim.x + threadIdx.x; idx < N;
         idx += (size_t)gridDim.x * blockDim.x) {
        size_t b = idx / ((size_t)TT * 36);
        size_t rem = idx % ((size_t)TT * 36);
        size_t t = rem / 36;
        int c = (int)(rem % 36);
        float v = 0.f;
        if (c < 30)      v = z[b * 30 + c] * masks[(b * TT + t) * 32 + c];
        else if (c < 32) v = tin2[(b * TT + t) * 2 + (c - 30)] * masks[(b * TT + t) * 32 + c];
        dec_in[idx] = v;
    }
}

__global__ void dense_kernel(const float* __restrict__ h6, const float* __restrict__ Wd,
                             const float* __restrict__ bd, const float* __restrict__ dec_masks,
                             float* __restrict__ out) {
    int gtid = blockIdx.x * blockDim.x + threadIdx.x;
    int row = gtid >> 5;
    int lane = gtid & 31;
    if (row >= BB * TT) return;
    float s = 0.f;
    const float* hrow = h6 + (size_t)row * 180;   // padded stride
    for (int k = lane; k < 175; k += 32) s = fmaf(hrow[k], Wd[k], s);
#pragma unroll
    for (int off = 16; off; off >>= 1) s += __shfl_down_sync(0xffffffffu, s, off);
    if (lane == 0) out[row] = tanhf(s + bd[0]) * dec_masks[row];
}

// ===================== host-side launch helper =====================
template <int H, int I, int NTH, bool HSIG, bool TANHA, bool UM, bool WSEQ>
static void launch_gru(const float* in_seq, const float* U, const float* W, const float* bias,
                       const float* mask, float* out_seq) {
    constexpr int BT = 4, JJT = 4;
    constexpr int HP = padDim(H), IP = padDim(I), KP = HP + IP;
    constexpr int JT = (H + 7) / 8;
    constexpr int JG = (JT + JJT - 1) / JJT;
    constexpr int JTp = JG * JJT;
    constexpr int SMTOT = JTp * 3 * KP + 2 * BT * KP + 4 * JTp + 2 * BT;
    constexpr int smem_bytes = SMTOT * 4;
    auto fn = gru_kernel<H, I, NTH, HSIG, TANHA, UM, WSEQ>;
    cudaFuncSetAttribute(fn, cudaFuncAttributeMaxDynamicSharedMemorySize, smem_bytes);
    cudaFuncSetAttribute(fn, cudaFuncAttributeNonPortableClusterSizeAllowed, 1);
    fn<<<256, NTH, smem_bytes>>>(in_seq, U, W, bias, mask, out_seq);
}

extern "C" void kernel_launch(void* const* d_in, const int* in_sizes, int n_in,
                              void* d_out, int out_size) {
    const float* x         = (const float*)d_in[0];
    const float* tin2      = (const float*)d_in[1];
    const float* masks     = (const float*)d_in[2];
    const float* dec_masks = (const float*)d_in[3];
    const float* eps       = (const float*)d_in[4];
    const float* W1 = (const float*)d_in[5];
    const float* U1 = (const float*)d_in[6];
    const float* b1 = (const float*)d_in[7];
    const float* W2 = (const float*)d_in[8];
    const float* U2 = (const float*)d_in[9];
    const float* b2 = (const float*)d_in[10];
    const float* W3 = (const float*)d_in[11];
    const float* U3 = (const float*)d_in[12];
    const float* b3 = (const float*)d_in[13];
    const float* W4 = (const float*)d_in[14];
    const float* U4 = (const float*)d_in[15];
    const float* b4 = (const float*)d_in[16];
    const float* W5 = (const float*)d_in[17];
    const float* U5 = (const float*)d_in[18];
    const float* b5 = (const float*)d_in[19];
    const float* W6 = (const float*)d_in[20];
    const float* U6 = (const float*)d_in[21];
    const float* b6 = (const float*)d_in[22];
    const float* Wd = (const float*)d_in[23];
    const float* bd = (const float*)d_in[24];
    float* out = (float*)d_out;

    void *pA, *pB, *pM, *pH34, *pZ, *pUc, *pWc, *pBc;
    cudaGetSymbolAddress(&pA, g_bufA);
    cudaGetSymbolAddress(&pB, g_bufB);
    cudaGetSymbolAddress(&pM, g_mask);
    cudaGetSymbolAddress(&pH34, g_h34);
    cudaGetSymbolAddress(&pZ, g_z);
    cudaGetSymbolAddress(&pUc, g_Uc);
    cudaGetSymbolAddress(&pWc, g_Wc);
    cudaGetSymbolAddress(&pBc, g_bc);
    float* bufA = (float*)pA;
    float* bufB = (float*)pB;
    float* mptr = (float*)pM;
    float* h34  = (float*)pH34;
    float* zbuf = (float*)pZ;
    float* Uc   = (float*)pUc;
    float* Wc   = (float*)pWc;
    float* Bc   = (float*)pBc;

    // prep
    mask_kernel<<<(BB * TT + 255) / 256, 256>>>(x, mptr);
    combine34_kernel<<<64, 256>>>(W3, U3, b3, W4, U4, b4, Uc, Wc, Bc);

    // encoder GRU1 (H=175, I=4): JT=22, JG=6 -> 192 threads
    launch_gru<175, 4, 192, true, true, true, true>(x, U1, W1, b1, mptr, bufA);

    // encoder GRU2 (H=150, I=175): JT=19, JG=5 -> 160 threads
    launch_gru<150, 175, 160, true, true, true, true>(bufA, U2, W2, b2, mptr, bufB);

    // fused GRU3+GRU4 (H=60, I=150): JT=8, JG=2 -> 64 threads, final state only
    launch_gru<60, 150, 64, false, false, true, false>(bufB, Uc, Wc, Bc, mptr, h34);

    // reparameterize + decoder input (stride 36)
    z_kernel<<<(BB * 30 + 255) / 256, 256>>>(h34, eps, zbuf);
    decin_kernel<<<2048, 256>>>(zbuf, tin2, masks, bufA);

    // decoder GRU5 (H=150, I=32): 160 threads
    launch_gru<150, 32, 160, true, true, false, true>(bufA, U5, W5, b5, nullptr, bufB);

    // decoder GRU6 (H=175, I=150): 192 threads
    launch_gru<175, 150, 192, true, true, false, true>(bufB, U6, W6, b6, nullptr, bufA);

    // dense head + output mask (stride 180)
    dense_kernel<<<(BB * TT + 7) / 8, 256>>>(bufA, Wd, bd, dec_masks, out);
}